// round 11
// baseline (speedup 1.0000x reference)
#include <cuda_runtime.h>
#include <cuda_bf16.h>
#include <math.h>
#include <stdint.h>

typedef unsigned long long ull;

// ---------------- f32x2 packed-math helpers ------------------------------------
__device__ __forceinline__ ull pack2(float lo, float hi) {
    ull r; asm("mov.b64 %0, {%1, %2};" : "=l"(r) : "f"(lo), "f"(hi)); return r;
}
__device__ __forceinline__ void unpack2(ull v, float& lo, float& hi) {
    asm("mov.b64 {%0, %1}, %2;" : "=f"(lo), "=f"(hi) : "l"(v));
}
__device__ __forceinline__ void fma2(ull& d, ull a, ull b) {
    asm("fma.rn.f32x2 %0, %1, %2, %0;" : "+l"(d) : "l"(a), "l"(b));
}

// ---------------- bf16 / mma helpers --------------------------------------------
__device__ __forceinline__ uint32_t packbf(float lo, float hi) {  // {lo->low16, hi->high16}
    uint32_t r; asm("cvt.rn.bf16x2.f32 %0, %1, %2;" : "=r"(r) : "f"(hi), "f"(lo)); return r;
}
__device__ __forceinline__ float loF(uint32_t u) { return __uint_as_float(u << 16); }
__device__ __forceinline__ float hiF(uint32_t u) { return __uint_as_float(u & 0xffff0000u); }
__device__ __forceinline__ float ex2f(float x) {
    float r; asm("ex2.approx.f32 %0, %1;" : "=f"(r) : "f"(x)); return r;
}

__device__ __forceinline__ uint32_t cvta_s(const void* p) {
    uint32_t a;
    asm("{ .reg .u64 t; cvta.to.shared.u64 t, %1; cvt.u32.u64 %0, t; }" : "=r"(a) : "l"(p));
    return a;
}
__device__ __forceinline__ void ldmx4(uint32_t* r, uint32_t a) {
    asm volatile("ldmatrix.sync.aligned.m8n8.x4.shared.b16 {%0,%1,%2,%3}, [%4];"
                 : "=r"(r[0]), "=r"(r[1]), "=r"(r[2]), "=r"(r[3]) : "r"(a));
}
__device__ __forceinline__ void mma16816(float* c, const uint32_t* a, uint32_t b0, uint32_t b1) {
    asm volatile(
        "mma.sync.aligned.m16n8k16.row.col.f32.bf16.bf16.f32 "
        "{%0,%1,%2,%3}, {%4,%5,%6,%7}, {%8,%9}, {%0,%1,%2,%3};"
        : "+f"(c[0]), "+f"(c[1]), "+f"(c[2]), "+f"(c[3])
        : "r"(a[0]), "r"(a[1]), "r"(a[2]), "r"(a[3]), "r"(b0), "r"(b1));
}
__device__ __forceinline__ void cpa16(uint32_t dst, const void* src) {
    asm volatile("cp.async.cg.shared.global [%0], [%1], 16;" :: "r"(dst), "l"(src) : "memory");
}
#define CP_COMMIT() asm volatile("cp.async.commit_group;" ::: "memory")
#define CP_WAIT0()  asm volatile("cp.async.wait_group 0;" ::: "memory")

// ---------------- problem constants -------------------------------------------
#define BB 8
#define CC 64
#define HC 32
#define NN 4096
#define LOG2E 1.4426950408889634f

// ---------------- device scratch -----------------------------------------------
__device__ __align__(16) float g_xq[BB * CC * NN];            // [b][c][n]
__device__ __align__(16) unsigned short g_qhi[BB * NN * HC];  // bf16(q*log2e) hi
__device__ __align__(16) unsigned short g_qlo[BB * NN * HC];  // residual
__device__ __align__(16) unsigned short g_khi[BB * NN * HC];
__device__ __align__(16) unsigned short g_klo[BB * NN * HC];
__device__ __align__(16) unsigned short g_vthi[BB * HC * NN]; // bf16 V^T [b][d][n]
__device__ __align__(16) unsigned short g_vtlo[BB * HC * NN];

// ---------------- kernel B: weight quant + x fake-quant + fused QKV -------------
__global__ void __launch_bounds__(128) k_xq_qkv(const float* __restrict__ x,
                                                const float* __restrict__ wq,
                                                const float* __restrict__ wk,
                                                const float* __restrict__ wv,
                                                const float* __restrict__ bq,
                                                const float* __restrict__ bk,
                                                const float* __restrict__ bv,
                                                const float* __restrict__ s_in_p) {
    extern __shared__ float smB[];
    float* xs = smB;                 // [64][128]
    float* ws = smB + CC * 128;      // [64][96]
    __shared__ float redw[12];
    const int t = threadIdx.x;
    const int b = blockIdx.y;
    const int n0 = blockIdx.x * 128;
    const float si = s_in_p[0];

    // ---- x fake-quant into smem + global ----
    const float* xb = x + ((size_t)b * CC) * NN + n0;
    float* xqb = g_xq + ((size_t)b * CC) * NN + n0;
#pragma unroll 4
    for (int c = 0; c < CC; c++) {
        float v = xb[c * NN + t];
        float r = rintf(v / si);
        r = fminf(fmaxf(r, -128.f), 127.f);
        float q = r * si;
        xqb[c * NN + t] = q;
        xs[c * 128 + t] = q;
    }

    // ---- per-tensor weight max-abs (redundant per block; deterministic) ----
    float mx0 = 0.f, mx1 = 0.f, mx2 = 0.f;
    for (int i = t; i < CC * HC; i += 128) {
        mx0 = fmaxf(mx0, fabsf(wq[i]));
        mx1 = fmaxf(mx1, fabsf(wk[i]));
        mx2 = fmaxf(mx2, fabsf(wv[i]));
    }
#pragma unroll
    for (int s = 16; s; s >>= 1) {
        mx0 = fmaxf(mx0, __shfl_xor_sync(0xffffffffu, mx0, s));
        mx1 = fmaxf(mx1, __shfl_xor_sync(0xffffffffu, mx1, s));
        mx2 = fmaxf(mx2, __shfl_xor_sync(0xffffffffu, mx2, s));
    }
    if ((t & 31) == 0) {
        redw[t >> 5] = mx0; redw[4 + (t >> 5)] = mx1; redw[8 + (t >> 5)] = mx2;
    }
    __syncthreads();
    float s0 = fmaxf(fmaxf(redw[0], redw[1]), fmaxf(redw[2], redw[3])) / 127.f;
    float s1 = fmaxf(fmaxf(redw[4], redw[5]), fmaxf(redw[6], redw[7])) / 127.f;
    float s2 = fmaxf(fmaxf(redw[8], redw[9]), fmaxf(redw[10], redw[11])) / 127.f;
    // quantize weights into transposed smem [c][96]
    for (int i = t; i < CC * HC; i += 128) {
        int hc = i >> 6, c = i & 63;
        ws[c * 96 + hc]      = fminf(fmaxf(rintf(wq[i] / s0), -127.f), 127.f) * s0;
        ws[c * 96 + 32 + hc] = fminf(fmaxf(rintf(wk[i] / s1), -127.f), 127.f) * s1;
        ws[c * 96 + 64 + hc] = fminf(fmaxf(rintf(wv[i] / s2), -127.f), 127.f) * s2;
    }
    __syncthreads();

    ull aq[16], ak[16], av[16];
#pragma unroll
    for (int h = 0; h < 16; h++) {
        aq[h] = pack2(bq[2 * h], bq[2 * h + 1]);
        ak[h] = pack2(bk[2 * h], bk[2 * h + 1]);
        av[h] = pack2(bv[2 * h], bv[2 * h + 1]);
    }
#pragma unroll 2
    for (int c = 0; c < CC; c++) {
        float xv = xs[c * 128 + t];
        ull xp = pack2(xv, xv);
        const ulonglong2* wr = (const ulonglong2*)(ws + c * 96);
#pragma unroll
        for (int j = 0; j < 8; j++) {
            ulonglong2 u = wr[j];
            fma2(aq[2 * j], xp, u.x);
            fma2(aq[2 * j + 1], xp, u.y);
        }
#pragma unroll
        for (int j = 0; j < 8; j++) {
            ulonglong2 u = wr[8 + j];
            fma2(ak[2 * j], xp, u.x);
            fma2(ak[2 * j + 1], xp, u.y);
        }
#pragma unroll
        for (int j = 0; j < 8; j++) {
            ulonglong2 u = wr[16 + j];
            fma2(av[2 * j], xp, u.x);
            fma2(av[2 * j + 1], xp, u.y);
        }
    }

    size_t bn = (size_t)b * NN + n0 + t;
    // Q scaled by log2e (exp -> single ex2 later); symmetric hi/lo for Q and K.
    uint32_t qh[16], ql[16], kh[16], kl[16];
#pragma unroll
    for (int j = 0; j < 16; j++) {
        float f0, f1;
        unpack2(aq[j], f0, f1);
        f0 *= LOG2E; f1 *= LOG2E;
        uint32_t u = packbf(f0, f1);
        qh[j] = u;
        ql[j] = packbf(f0 - loF(u), f1 - hiF(u));
        unpack2(ak[j], f0, f1);
        u = packbf(f0, f1);
        kh[j] = u;
        kl[j] = packbf(f0 - loF(u), f1 - hiF(u));
    }
    uint4* qhp = (uint4*)(g_qhi + bn * HC);
    uint4* qlp = (uint4*)(g_qlo + bn * HC);
    uint4* khp = (uint4*)(g_khi + bn * HC);
    uint4* klp = (uint4*)(g_klo + bn * HC);
#pragma unroll
    for (int c4 = 0; c4 < 4; c4++) {
        uint4 u;
        u.x = qh[4 * c4]; u.y = qh[4 * c4 + 1]; u.z = qh[4 * c4 + 2]; u.w = qh[4 * c4 + 3];
        qhp[c4] = u;
        u.x = ql[4 * c4]; u.y = ql[4 * c4 + 1]; u.z = ql[4 * c4 + 2]; u.w = ql[4 * c4 + 3];
        qlp[c4] = u;
        u.x = kh[4 * c4]; u.y = kh[4 * c4 + 1]; u.z = kh[4 * c4 + 2]; u.w = kh[4 * c4 + 3];
        khp[c4] = u;
        u.x = kl[4 * c4]; u.y = kl[4 * c4 + 1]; u.z = kl[4 * c4 + 2]; u.w = kl[4 * c4 + 3];
        klp[c4] = u;
    }
    unsigned short* vh = g_vthi + (size_t)b * HC * NN + n0 + t;
    unsigned short* vl = g_vtlo + (size_t)b * HC * NN + n0 + t;
#pragma unroll
    for (int j = 0; j < 16; j++) {
        float f0, f1;
        unpack2(av[j], f0, f1);
        uint32_t u = packbf(f0, f1);
        uint32_t r = packbf(f0 - loF(u), f1 - hiF(u));
        vh[(size_t)(2 * j) * NN] = (unsigned short)(u & 0xffffu);
        vh[(size_t)(2 * j + 1) * NN] = (unsigned short)(u >> 16);
        vl[(size_t)(2 * j) * NN] = (unsigned short)(r & 0xffffu);
        vl[(size_t)(2 * j + 1) * NN] = (unsigned short)(r >> 16);
    }
}

// ---------------- kernel C: HMMA flash attention + fused proj ---------------------
// grid (16, 8) = (q-tile 256, batch), 512 threads / 16 warps, 16 q-rows per warp.
// 4 warps/SMSP for latency hiding; same total MMA work as the 256-thread variant
// but half the per-warp register state -> fits the 128-reg cap of 512 threads.
#define SM_QHI 0            // 256 rows x 80B
#define SM_QLO 20480
#define SM_K   40960        // + buf*10240 : KHI 64x80, KLO at +5120
#define SM_V   61440        // + buf*9216  : VHI 32x144, VLO at +4608
#define SM_Z   40960        // epilogue reuse: 256 x 34 f32
#define SM_WP  79872        // wp quantized 64x32 f32
#define SM_BP  88064        // bp 64 f32
#define ATTN_SMEM 88320

__global__ void __launch_bounds__(512, 1) k_attn(const float* __restrict__ wp,
                                                 const float* __restrict__ bp,
                                                 const float* __restrict__ s_in_p,
                                                 const float* __restrict__ s_out_p,
                                                 float* __restrict__ out) {
    extern __shared__ char sm[];
    __shared__ float redp[16];
    uint32_t sb = cvta_s(sm);
    const int t = threadIdx.x;
    const int w = t >> 5, lane = t & 31;
    const int b = blockIdx.y, qt = blockIdx.x;
    const int q0 = w * 16;

    const char* pkhi = (const char*)g_khi + (size_t)b * NN * 64;
    const char* pklo = (const char*)g_klo + (size_t)b * NN * 64;
    const char* pvhi = (const char*)g_vthi + (size_t)b * HC * (NN * 2);
    const char* pvlo = (const char*)g_vtlo + (size_t)b * HC * (NN * 2);

    // staging: K 512 + V 512 = 1024 cp.async of 16B; 512 threads x 2
    auto stageKV = [&](int kt) {
        uint32_t kb = sb + SM_K + (kt & 1) * 10240;
        uint32_t vb = sb + SM_V + (kt & 1) * 9216;
#pragma unroll
        for (int i = 0; i < 2; i++) {
            int idx = t + i * 512;
            if (idx < 512) {
                int part = idx >> 8, rem = idx & 255;
                int row = rem >> 2, ch = rem & 3;
                const char* src = (part ? pklo : pkhi) + (size_t)(kt * 64 + row) * 64 + ch * 16;
                cpa16(kb + part * 5120 + row * 80 + ch * 16, src);
            } else {
                int part = (idx >> 8) - 2, rem = idx & 255;
                int d = rem >> 3, ch = rem & 7;
                const char* src = (part ? pvlo : pvhi) + (size_t)d * (NN * 2) + kt * 128 + ch * 16;
                cpa16(vb + part * 4608 + d * 144 + ch * 16, src);
            }
        }
    };

    // ---- prologue: stage Q + KV(0); quantize wp while cp.async flies ----
    {
        const char* pqhi = (const char*)g_qhi + (size_t)b * NN * 64;
        const char* pqlo = (const char*)g_qlo + (size_t)b * NN * 64;
#pragma unroll
        for (int i = 0; i < 4; i++) {
            int idx = t + i * 512;
            int part = idx >> 10, rem = idx & 1023;
            int row = rem >> 2, ch = rem & 3;
            const char* src = (part ? pqlo : pqhi) + (size_t)(qt * 256 + row) * 64 + ch * 16;
            cpa16(sb + SM_QHI + part * 20480 + row * 80 + ch * 16, src);
        }
    }
    stageKV(0);
    CP_COMMIT();
    {
        float mxp = 0.f;
        for (int i = t; i < CC * HC; i += 512) mxp = fmaxf(mxp, fabsf(wp[i]));
#pragma unroll
        for (int s = 16; s; s >>= 1) mxp = fmaxf(mxp, __shfl_xor_sync(0xffffffffu, mxp, s));
        if (lane == 0) redp[w] = mxp;
        __syncthreads();
        float m01 = fmaxf(fmaxf(redp[0], redp[1]), fmaxf(redp[2], redp[3]));
        float m23 = fmaxf(fmaxf(redp[4], redp[5]), fmaxf(redp[6], redp[7]));
        float m45 = fmaxf(fmaxf(redp[8], redp[9]), fmaxf(redp[10], redp[11]));
        float m67 = fmaxf(fmaxf(redp[12], redp[13]), fmaxf(redp[14], redp[15]));
        float sp = fmaxf(fmaxf(m01, m23), fmaxf(m45, m67)) / 127.f;
        float* wsp = (float*)(sm + SM_WP);
        for (int i = t; i < CC * HC; i += 512)
            wsp[i] = fminf(fmaxf(rintf(wp[i] / sp), -127.f), 127.f) * sp;
        if (t < CC) ((float*)(sm + SM_BP))[t] = bp[t];
    }
    CP_WAIT0();
    __syncthreads();

    // Q fragments (1 m-tile x 2 k16 chunks, hi + lo)
    uint32_t qfh[2][4], qfl[2][4];
    {
        uint32_t qa = sb + SM_QHI +
            (uint32_t)((q0 + (lane & 7) + ((lane >> 3) & 1) * 8) * 80 +
                       ((lane >> 4) & 1) * 16);
        ldmx4(qfh[0], qa);
        ldmx4(qfh[1], qa + 32);
        ldmx4(qfl[0], qa + 20480);
        ldmx4(qfl[1], qa + 20480 + 32);
    }

    float O[4][4];
    float l_acc[2] = {0.f, 0.f};
#pragma unroll
    for (int n = 0; n < 4; n++)
#pragma unroll
        for (int i = 0; i < 4; i++) O[n][i] = 0.f;

    // ---- main loop: 64 tiles of 64 keys ----
    for (int kt = 0; kt < 64; kt++) {
        uint32_t kb = sb + SM_K + (kt & 1) * 10240;
        uint32_t vb = sb + SM_V + (kt & 1) * 9216;
        if (kt < 63) { stageKV(kt + 1); CP_COMMIT(); }

        // K x4 fragment: r0,r1 = ks0 (dims 0-15), r2,r3 = ks1 (dims 16-31)
        const uint32_t ka0 = kb + (uint32_t)((lane & 7) * 80 + (lane >> 3) * 16);

        // S = Q K^T (hi*hi + lo*hi + hi*lo); TLP (4 warps/SMSP) hides LDS latency
        float S[8][4];
#pragma unroll
        for (int j = 0; j < 8; j++)
#pragma unroll
            for (int i = 0; i < 4; i++) S[j][i] = 0.f;

#pragma unroll
        for (int j = 0; j < 8; j++) {
            uint32_t kfh[4], kfl[4];
            ldmx4(kfh, ka0 + (uint32_t)(j * 8 * 80));
            ldmx4(kfl, ka0 + (uint32_t)(j * 8 * 80) + 5120);
            mma16816(S[j], qfh[0], kfh[0], kfh[1]);
            mma16816(S[j], qfl[0], kfh[0], kfh[1]);
            mma16816(S[j], qfh[0], kfl[0], kfl[1]);
            mma16816(S[j], qfh[1], kfh[2], kfh[3]);
            mma16816(S[j], qfl[1], kfh[2], kfh[3]);
            mma16816(S[j], qfh[1], kfl[2], kfl[3]);
        }

        // V x4 fragment base: n-pair via +16*144
        const uint32_t va0 = vb +
            (uint32_t)((((lane >> 4) & 1) * 8 + (lane & 7)) * 144 + ((lane >> 3) & 1) * 16);

        // PV in 16-key chunks: V loads hoisted above exp/pack
#pragma unroll
        for (int kk = 0; kk < 4; kk++) {
            uint32_t vfh[8], vfl[8];
            ldmx4(vfh, va0 + kk * 32);                 // n 0-1
            ldmx4(vfh + 4, va0 + kk * 32 + 16 * 144);  // n 2-3
            ldmx4(vfl, va0 + 4608 + kk * 32);
            ldmx4(vfl + 4, va0 + 4608 + kk * 32 + 16 * 144);

            uint32_t phi[4], plo[4];
            {
                const int j0 = 2 * kk, j1 = 2 * kk + 1;
                float e0 = ex2f(S[j0][0]);
                float e1 = ex2f(S[j0][1]);
                float e2 = ex2f(S[j0][2]);
                float e3 = ex2f(S[j0][3]);
                float e4 = ex2f(S[j1][0]);
                float e5 = ex2f(S[j1][1]);
                float e6 = ex2f(S[j1][2]);
                float e7 = ex2f(S[j1][3]);
                l_acc[0] += (e0 + e1) + (e4 + e5);
                l_acc[1] += (e2 + e3) + (e6 + e7);
                uint32_t u;
                u = packbf(e0, e1); phi[0] = u;
                plo[0] = packbf(e0 - loF(u), e1 - hiF(u));
                u = packbf(e2, e3); phi[1] = u;
                plo[1] = packbf(e2 - loF(u), e3 - hiF(u));
                u = packbf(e4, e5); phi[2] = u;
                plo[2] = packbf(e4 - loF(u), e5 - hiF(u));
                u = packbf(e6, e7); phi[3] = u;
                plo[3] = packbf(e6 - loF(u), e7 - hiF(u));
            }
#pragma unroll
            for (int n = 0; n < 4; n++) {
                uint32_t b0 = vfh[2 * n], b1 = vfh[2 * n + 1];
                uint32_t c0 = vfl[2 * n], c1 = vfl[2 * n + 1];
                mma16816(O[n], phi, b0, b1);
                mma16816(O[n], plo, b0, b1);
                mma16816(O[n], phi, c0, c1);
            }
        }

        if (kt < 63) CP_WAIT0();
        __syncthreads();
    }

    // ---- epilogue 1: l-reduce, normalize, fake-quant z, stage to smem ----
    const float si = s_in_p[0];
    const float so = s_out_p[0];
    float* zs = (float*)(sm + SM_Z);
#pragma unroll
    for (int h = 0; h < 2; h++) {
        float lv = l_acc[h];
        lv += __shfl_xor_sync(0xffffffffu, lv, 1);
        lv += __shfl_xor_sync(0xffffffffu, lv, 2);
        float inv = 1.0f / lv;
        int row = q0 + (lane >> 2) + h * 8;
#pragma unroll
        for (int n = 0; n < 4; n++) {
            float z0 = O[n][h * 2 + 0] * inv;
            float z1 = O[n][h * 2 + 1] * inv;
            float r0 = fminf(fmaxf(rintf(z0 / si), -128.f), 127.f) * si;
            float r1 = fminf(fmaxf(rintf(z1 / si), -128.f), 127.f) * si;
            float2 u; u.x = r0; u.y = r1;
            *(float2*)(zs + row * 34 + n * 8 + (lane & 3) * 2) = u;
        }
    }
    __syncthreads();

    // ---- epilogue 2: output proj + residual + out fq (thread = pixel x 32-ch half) --
    {
        const int px = t & 255, chh = t >> 8;   // chh in 0..1 -> channels chh*32..+31
        ull zp[16];
#pragma unroll
        for (int j = 0; j < 16; j++)
            zp[j] = pack2(zs[px * 34 + 2 * j], zs[px * 34 + 2 * j + 1]);
        const float* wsp = (const float*)(sm + SM_WP);
        const float* bps = (const float*)(sm + SM_BP);
        const float* xqb = g_xq + ((size_t)b * CC + chh * 32) * NN + qt * 256 + px;
        float* ob = out + ((size_t)b * CC + chh * 32) * NN + qt * 256 + px;
#pragma unroll
        for (int c0 = 0; c0 < 32; c0 += 16) {
            float xv[16];
#pragma unroll
            for (int u = 0; u < 16; u++) xv[u] = xqb[(size_t)(c0 + u) * NN];
#pragma unroll
            for (int u = 0; u < 16; u++) {
                int c = chh * 32 + c0 + u;
                ull a0 = 0ull, a1 = 0ull;
                const ulonglong2* wr = (const ulonglong2*)(wsp + c * HC);
#pragma unroll
                for (int j = 0; j < 8; j++) {
                    ulonglong2 uu = wr[j];
                    fma2(a0, zp[2 * j], uu.x);
                    fma2(a1, zp[2 * j + 1], uu.y);
                }
                float f0, f1, f2, f3;
                unpack2(a0, f0, f1);
                unpack2(a1, f2, f3);
                float val = xv[u] + (f0 + f1) + (f2 + f3) + bps[c];
                float r = rintf(val / so);
                r = fminf(fmaxf(r, -128.f), 127.f);
                ob[(size_t)(c0 + u) * NN] = r * so;
            }
        }
    }
}

// ---------------- launch ----------------------------------------------------------
extern "C" void kernel_launch(void* const* d_in, const int* in_sizes, int n_in,
                              void* d_out, int out_size) {
    const float* x     = (const float*)d_in[0];
    const float* wq    = (const float*)d_in[1];
    const float* bq    = (const float*)d_in[2];
    const float* wk    = (const float*)d_in[3];
    const float* bk    = (const float*)d_in[4];
    const float* wv    = (const float*)d_in[5];
    const float* bv    = (const float*)d_in[6];
    const float* wp    = (const float*)d_in[7];
    const float* bp    = (const float*)d_in[8];
    const float* s_in  = (const float*)d_in[9];
    const float* s_out = (const float*)d_in[10];
    float* out = (float*)d_out;

    const int smemB = (CC * 128 + CC * 96) * 4;
    cudaFuncSetAttribute(k_xq_qkv, cudaFuncAttributeMaxDynamicSharedMemorySize, smemB);
    cudaFuncSetAttribute(k_attn, cudaFuncAttributeMaxDynamicSharedMemorySize, ATTN_SMEM);

    k_xq_qkv<<<dim3(32, 8), 128, smemB>>>(x, wq, wk, wv, bq, bk, bv, s_in);
    k_attn<<<dim3(16, 8), 512, ATTN_SMEM>>>(wp, bp, s_in, s_out, out);
}

// round 12
// speedup vs baseline: 1.2989x; 1.2989x over previous
#include <cuda_runtime.h>
#include <cuda_fp16.h>
#include <math.h>
#include <stdint.h>

typedef unsigned long long ull;

// ---------------- f32x2 packed-math helpers ------------------------------------
__device__ __forceinline__ ull pack2(float lo, float hi) {
    ull r; asm("mov.b64 %0, {%1, %2};" : "=l"(r) : "f"(lo), "f"(hi)); return r;
}
__device__ __forceinline__ void unpack2(ull v, float& lo, float& hi) {
    asm("mov.b64 {%0, %1}, %2;" : "=f"(lo), "=f"(hi) : "l"(v));
}
__device__ __forceinline__ void fma2(ull& d, ull a, ull b) {
    asm("fma.rn.f32x2 %0, %1, %2, %0;" : "+l"(d) : "l"(a), "l"(b));
}

// ---------------- fp16 / mma helpers ---------------------------------------------
__device__ __forceinline__ uint32_t packh(float lo, float hi) {  // {lo->low16, hi->high16}
    uint32_t r; asm("cvt.rn.f16x2.f32 %0, %1, %2;" : "=r"(r) : "f"(hi), "f"(lo)); return r;
}
__device__ __forceinline__ float loH(uint32_t u) {
    float f; asm("{.reg .f16 l,h; mov.b32 {l,h}, %1; cvt.f32.f16 %0, l;}" : "=f"(f) : "r"(u));
    return f;
}
__device__ __forceinline__ float hiH(uint32_t u) {
    float f; asm("{.reg .f16 l,h; mov.b32 {l,h}, %1; cvt.f32.f16 %0, h;}" : "=f"(f) : "r"(u));
    return f;
}
__device__ __forceinline__ float ex2f(float x) {
    float r; asm("ex2.approx.f32 %0, %1;" : "=f"(r) : "f"(x)); return r;
}

__device__ __forceinline__ uint32_t cvta_s(const void* p) {
    uint32_t a;
    asm("{ .reg .u64 t; cvta.to.shared.u64 t, %1; cvt.u32.u64 %0, t; }" : "=r"(a) : "l"(p));
    return a;
}
__device__ __forceinline__ void ldmx4(uint32_t* r, uint32_t a) {
    asm volatile("ldmatrix.sync.aligned.m8n8.x4.shared.b16 {%0,%1,%2,%3}, [%4];"
                 : "=r"(r[0]), "=r"(r[1]), "=r"(r[2]), "=r"(r[3]) : "r"(a));
}
__device__ __forceinline__ void mma16816(float* c, const uint32_t* a, uint32_t b0, uint32_t b1) {
    asm volatile(
        "mma.sync.aligned.m16n8k16.row.col.f32.f16.f16.f32 "
        "{%0,%1,%2,%3}, {%4,%5,%6,%7}, {%8,%9}, {%0,%1,%2,%3};"
        : "+f"(c[0]), "+f"(c[1]), "+f"(c[2]), "+f"(c[3])
        : "r"(a[0]), "r"(a[1]), "r"(a[2]), "r"(a[3]), "r"(b0), "r"(b1));
}
__device__ __forceinline__ void cpa16(uint32_t dst, const void* src) {
    asm volatile("cp.async.cg.shared.global [%0], [%1], 16;" :: "r"(dst), "l"(src) : "memory");
}
#define CP_COMMIT() asm volatile("cp.async.commit_group;" ::: "memory")
#define CP_WAIT0()  asm volatile("cp.async.wait_group 0;" ::: "memory")

// ---------------- problem constants -------------------------------------------
#define BB 8
#define CC 64
#define HC 32
#define NN 4096
#define LOG2E 1.4426950408889634f
#define PSHIFT 16.0f   // P' = 2^(S*log2e - 16); cancels exactly in O/l

// ---------------- device scratch -----------------------------------------------
__device__ __align__(16) float g_xq[BB * CC * NN];            // [b][c][n]
__device__ __align__(16) unsigned short g_qhi[BB * NN * HC];  // fp16(q*log2e) hi
__device__ __align__(16) unsigned short g_qlo[BB * NN * HC];  // fp16 residual
__device__ __align__(16) unsigned short g_khi[BB * NN * HC];  // fp16 K
__device__ __align__(16) unsigned short g_vthi[BB * HC * NN]; // fp16 V^T [b][d][n]

// ---------------- kernel B: weight quant + x fake-quant + fused QKV -------------
__global__ void __launch_bounds__(128) k_xq_qkv(const float* __restrict__ x,
                                                const float* __restrict__ wq,
                                                const float* __restrict__ wk,
                                                const float* __restrict__ wv,
                                                const float* __restrict__ bq,
                                                const float* __restrict__ bk,
                                                const float* __restrict__ bv,
                                                const float* __restrict__ s_in_p) {
    extern __shared__ float smB[];
    float* xs = smB;                 // [64][128]
    float* ws = smB + CC * 128;      // [64][96]
    __shared__ float redw[12];
    const int t = threadIdx.x;
    const int b = blockIdx.y;
    const int n0 = blockIdx.x * 128;
    const float si = s_in_p[0];

    // ---- x fake-quant into smem + global ----
    const float* xb = x + ((size_t)b * CC) * NN + n0;
    float* xqb = g_xq + ((size_t)b * CC) * NN + n0;
#pragma unroll 4
    for (int c = 0; c < CC; c++) {
        float v = xb[c * NN + t];
        float r = rintf(v / si);
        r = fminf(fmaxf(r, -128.f), 127.f);
        float q = r * si;
        xqb[c * NN + t] = q;
        xs[c * 128 + t] = q;
    }

    // ---- per-tensor weight max-abs (redundant per block; deterministic) ----
    float mx0 = 0.f, mx1 = 0.f, mx2 = 0.f;
    for (int i = t; i < CC * HC; i += 128) {
        mx0 = fmaxf(mx0, fabsf(wq[i]));
        mx1 = fmaxf(mx1, fabsf(wk[i]));
        mx2 = fmaxf(mx2, fabsf(wv[i]));
    }
#pragma unroll
    for (int s = 16; s; s >>= 1) {
        mx0 = fmaxf(mx0, __shfl_xor_sync(0xffffffffu, mx0, s));
        mx1 = fmaxf(mx1, __shfl_xor_sync(0xffffffffu, mx1, s));
        mx2 = fmaxf(mx2, __shfl_xor_sync(0xffffffffu, mx2, s));
    }
    if ((t & 31) == 0) {
        redw[t >> 5] = mx0; redw[4 + (t >> 5)] = mx1; redw[8 + (t >> 5)] = mx2;
    }
    __syncthreads();
    float s0 = fmaxf(fmaxf(redw[0], redw[1]), fmaxf(redw[2], redw[3])) / 127.f;
    float s1 = fmaxf(fmaxf(redw[4], redw[5]), fmaxf(redw[6], redw[7])) / 127.f;
    float s2 = fmaxf(fmaxf(redw[8], redw[9]), fmaxf(redw[10], redw[11])) / 127.f;
    // quantize weights into transposed smem [c][96]
    for (int i = t; i < CC * HC; i += 128) {
        int hc = i >> 6, c = i & 63;
        ws[c * 96 + hc]      = fminf(fmaxf(rintf(wq[i] / s0), -127.f), 127.f) * s0;
        ws[c * 96 + 32 + hc] = fminf(fmaxf(rintf(wk[i] / s1), -127.f), 127.f) * s1;
        ws[c * 96 + 64 + hc] = fminf(fmaxf(rintf(wv[i] / s2), -127.f), 127.f) * s2;
    }
    __syncthreads();

    ull aq[16], ak[16], av[16];
#pragma unroll
    for (int h = 0; h < 16; h++) {
        aq[h] = pack2(bq[2 * h], bq[2 * h + 1]);
        ak[h] = pack2(bk[2 * h], bk[2 * h + 1]);
        av[h] = pack2(bv[2 * h], bv[2 * h + 1]);
    }
#pragma unroll 2
    for (int c = 0; c < CC; c++) {
        float xv = xs[c * 128 + t];
        ull xp = pack2(xv, xv);
        const ulonglong2* wr = (const ulonglong2*)(ws + c * 96);
#pragma unroll
        for (int j = 0; j < 8; j++) {
            ulonglong2 u = wr[j];
            fma2(aq[2 * j], xp, u.x);
            fma2(aq[2 * j + 1], xp, u.y);
        }
#pragma unroll
        for (int j = 0; j < 8; j++) {
            ulonglong2 u = wr[8 + j];
            fma2(ak[2 * j], xp, u.x);
            fma2(ak[2 * j + 1], xp, u.y);
        }
#pragma unroll
        for (int j = 0; j < 8; j++) {
            ulonglong2 u = wr[16 + j];
            fma2(av[2 * j], xp, u.x);
            fma2(av[2 * j + 1], xp, u.y);
        }
    }

    size_t bn = (size_t)b * NN + n0 + t;
    // Q scaled by log2e, fp16 hi + residual lo. K single fp16.
    uint32_t qh[16], ql[16], kh[16];
#pragma unroll
    for (int j = 0; j < 16; j++) {
        float f0, f1;
        unpack2(aq[j], f0, f1);
        f0 *= LOG2E; f1 *= LOG2E;
        uint32_t u = packh(f0, f1);
        qh[j] = u;
        ql[j] = packh(f0 - loH(u), f1 - hiH(u));
        unpack2(ak[j], f0, f1);
        kh[j] = packh(f0, f1);
    }
    uint4* qhp = (uint4*)(g_qhi + bn * HC);
    uint4* qlp = (uint4*)(g_qlo + bn * HC);
    uint4* khp = (uint4*)(g_khi + bn * HC);
#pragma unroll
    for (int c4 = 0; c4 < 4; c4++) {
        uint4 u;
        u.x = qh[4 * c4]; u.y = qh[4 * c4 + 1]; u.z = qh[4 * c4 + 2]; u.w = qh[4 * c4 + 3];
        qhp[c4] = u;
        u.x = ql[4 * c4]; u.y = ql[4 * c4 + 1]; u.z = ql[4 * c4 + 2]; u.w = ql[4 * c4 + 3];
        qlp[c4] = u;
        u.x = kh[4 * c4]; u.y = kh[4 * c4 + 1]; u.z = kh[4 * c4 + 2]; u.w = kh[4 * c4 + 3];
        khp[c4] = u;
    }
    // V transposed, single fp16
    unsigned short* vh = g_vthi + (size_t)b * HC * NN + n0 + t;
#pragma unroll
    for (int j = 0; j < 16; j++) {
        float f0, f1;
        unpack2(av[j], f0, f1);
        uint32_t u = packh(f0, f1);
        vh[(size_t)(2 * j) * NN] = (unsigned short)(u & 0xffffu);
        vh[(size_t)(2 * j + 1) * NN] = (unsigned short)(u >> 16);
    }
}

// ---------------- kernel C: HMMA flash attention + fused proj ---------------------
// grid (16, 8) = (q-tile 256, batch), 256 threads / 8 warps, 32 q-rows per warp.
// FP16 2-MMA scheme: S = (Qhi+Qlo)*Kfp16, O = (Phi+Plo)*Vfp16 -> 256 MMA/SMSP/kt.
// P exponent-shifted by 2^-16 (exact cancellation in O/l) to fit fp16 range.
#define SM_QHI 0            // 256 rows x 80B
#define SM_QLO 20480
#define SM_K   40960        // + buf*5120 : K 64x80
#define SM_V   51200        // + buf*4608 : V 32x144
#define SM_WP  60416        // wp quantized 64x32 f32
#define SM_BP  68608        // bp 64 f32
#define ATTN_SMEM 68864
// epilogue zs (256x34 f32 = 34816B) reuses the Q region

__global__ void __launch_bounds__(256, 1) k_attn(const float* __restrict__ wp,
                                                 const float* __restrict__ bp,
                                                 const float* __restrict__ s_in_p,
                                                 const float* __restrict__ s_out_p,
                                                 float* __restrict__ out) {
    extern __shared__ char sm[];
    __shared__ float redp[8];
    uint32_t sb = cvta_s(sm);
    const int t = threadIdx.x;
    const int w = t >> 5, lane = t & 31;
    const int b = blockIdx.y, qt = blockIdx.x;
    const int q0 = w * 32;

    const char* pkhi = (const char*)g_khi + (size_t)b * NN * 64;
    const char* pvhi = (const char*)g_vthi + (size_t)b * HC * (NN * 2);

    // staging: K 256 + V 256 = 512 cp.async of 16B; 256 threads x 2
    auto stageKV = [&](int kt) {
        uint32_t kb = sb + SM_K + (kt & 1) * 5120;
        uint32_t vb = sb + SM_V + (kt & 1) * 4608;
#pragma unroll
        for (int i = 0; i < 2; i++) {
            int idx = t + i * 256;
            if (idx < 256) {
                int row = idx >> 2, ch = idx & 3;
                cpa16(kb + row * 80 + ch * 16,
                      pkhi + (size_t)(kt * 64 + row) * 64 + ch * 16);
            } else {
                int rem = idx & 255;
                int d = rem >> 3, ch = rem & 7;
                cpa16(vb + d * 144 + ch * 16,
                      pvhi + (size_t)d * (NN * 2) + kt * 128 + ch * 16);
            }
        }
    };

    // ---- prologue: stage Q + KV(0); quantize wp while cp.async flies ----
    {
        const char* pqhi = (const char*)g_qhi + (size_t)b * NN * 64;
        const char* pqlo = (const char*)g_qlo + (size_t)b * NN * 64;
#pragma unroll
        for (int i = 0; i < 8; i++) {
            int idx = t + i * 256;
            int part = idx >> 10, rem = idx & 1023;
            int row = rem >> 2, ch = rem & 3;
            const char* src = (part ? pqlo : pqhi) + (size_t)(qt * 256 + row) * 64 + ch * 16;
            cpa16(sb + SM_QHI + part * 20480 + row * 80 + ch * 16, src);
        }
    }
    stageKV(0);
    CP_COMMIT();
    {
        float mxp = 0.f;
        for (int i = t; i < CC * HC; i += 256) mxp = fmaxf(mxp, fabsf(wp[i]));
#pragma unroll
        for (int s = 16; s; s >>= 1) mxp = fmaxf(mxp, __shfl_xor_sync(0xffffffffu, mxp, s));
        if (lane == 0) redp[w] = mxp;
        __syncthreads();
        float sp = fmaxf(fmaxf(fmaxf(redp[0], redp[1]), fmaxf(redp[2], redp[3])),
                         fmaxf(fmaxf(redp[4], redp[5]), fmaxf(redp[6], redp[7]))) / 127.f;
        float* wsp = (float*)(sm + SM_WP);
        for (int i = t; i < CC * HC; i += 256)
            wsp[i] = fminf(fmaxf(rintf(wp[i] / sp), -127.f), 127.f) * sp;
        if (t < CC) ((float*)(sm + SM_BP))[t] = bp[t];
    }
    CP_WAIT0();
    __syncthreads();

    // Q fragments (2 m-tiles x 2 k16 chunks, hi + lo) via ldmatrix.x4
    uint32_t qfh[2][2][4], qfl[2][2][4];
#pragma unroll
    for (int m = 0; m < 2; m++) {
        uint32_t qa = sb + SM_QHI +
            (uint32_t)((q0 + m * 16 + (lane & 7) + ((lane >> 3) & 1) * 8) * 80 +
                       ((lane >> 4) & 1) * 16);
        ldmx4(qfh[m][0], qa);
        ldmx4(qfh[m][1], qa + 32);
        ldmx4(qfl[m][0], qa + 20480);
        ldmx4(qfl[m][1], qa + 20480 + 32);
    }

    float O[2][4][4];
    float l_acc[2][2] = {{0.f, 0.f}, {0.f, 0.f}};
#pragma unroll
    for (int m = 0; m < 2; m++)
#pragma unroll
        for (int n = 0; n < 4; n++)
#pragma unroll
            for (int i = 0; i < 4; i++) O[m][n][i] = 0.f;

    // ---- main loop: 64 tiles of 64 keys ----
    for (int kt = 0; kt < 64; kt++) {
        uint32_t kb = sb + SM_K + (kt & 1) * 5120;
        uint32_t vb = sb + SM_V + (kt & 1) * 4608;
        if (kt < 63) { stageKV(kt + 1); CP_COMMIT(); }

        const uint32_t ka0 = kb + (uint32_t)((lane & 7) * 80 + (lane >> 3) * 16);

        // S = (Qhi + Qlo) * K, single-fp16 K, depth-1 K-fragment prefetch
        float S[2][8][4];
#pragma unroll
        for (int m = 0; m < 2; m++)
#pragma unroll
            for (int j = 0; j < 8; j++)
#pragma unroll
                for (int i = 0; i < 4; i++) S[m][j][i] = 0.f;

        uint32_t kf[2][4];
        ldmx4(kf[0], ka0);
#pragma unroll
        for (int j = 0; j < 8; j++) {
            const int cur = j & 1, nxt = cur ^ 1;
            if (j < 7) ldmx4(kf[nxt], ka0 + (uint32_t)((j + 1) * 8 * 80));
            // ks = 0 (dims 0-15)
            mma16816(S[0][j], qfh[0][0], kf[cur][0], kf[cur][1]);
            mma16816(S[0][j], qfl[0][0], kf[cur][0], kf[cur][1]);
            mma16816(S[1][j], qfh[1][0], kf[cur][0], kf[cur][1]);
            mma16816(S[1][j], qfl[1][0], kf[cur][0], kf[cur][1]);
            // ks = 1 (dims 16-31)
            mma16816(S[0][j], qfh[0][1], kf[cur][2], kf[cur][3]);
            mma16816(S[0][j], qfl[0][1], kf[cur][2], kf[cur][3]);
            mma16816(S[1][j], qfh[1][1], kf[cur][2], kf[cur][3]);
            mma16816(S[1][j], qfl[1][1], kf[cur][2], kf[cur][3]);
        }

        const uint32_t va0 = vb +
            (uint32_t)((((lane >> 4) & 1) * 8 + (lane & 7)) * 144 + ((lane >> 3) & 1) * 16);

        // PV in 16-key chunks: V loads hoisted above exp/pack
#pragma unroll
        for (int kk = 0; kk < 4; kk++) {
            uint32_t vf[8];
            ldmx4(vf, va0 + kk * 32);                 // n 0-1
            ldmx4(vf + 4, va0 + kk * 32 + 16 * 144);  // n 2-3

            uint32_t phi[2][4], plo[2][4];
#pragma unroll
            for (int m = 0; m < 2; m++) {
                const int j0 = 2 * kk, j1 = 2 * kk + 1;
                float e0 = ex2f(S[m][j0][0] - PSHIFT);
                float e1 = ex2f(S[m][j0][1] - PSHIFT);
                float e2 = ex2f(S[m][j0][2] - PSHIFT);
                float e3 = ex2f(S[m][j0][3] - PSHIFT);
                float e4 = ex2f(S[m][j1][0] - PSHIFT);
                float e5 = ex2f(S[m][j1][1] - PSHIFT);
                float e6 = ex2f(S[m][j1][2] - PSHIFT);
                float e7 = ex2f(S[m][j1][3] - PSHIFT);
                l_acc[m][0] += (e0 + e1) + (e4 + e5);
                l_acc[m][1] += (e2 + e3) + (e6 + e7);
                uint32_t u;
                u = packh(e0, e1); phi[m][0] = u;
                plo[m][0] = packh(e0 - loH(u), e1 - hiH(u));
                u = packh(e2, e3); phi[m][1] = u;
                plo[m][1] = packh(e2 - loH(u), e3 - hiH(u));
                u = packh(e4, e5); phi[m][2] = u;
                plo[m][2] = packh(e4 - loH(u), e5 - hiH(u));
                u = packh(e6, e7); phi[m][3] = u;
                plo[m][3] = packh(e6 - loH(u), e7 - hiH(u));
            }
#pragma unroll
            for (int n = 0; n < 4; n++) {
                uint32_t b0 = vf[2 * n], b1 = vf[2 * n + 1];
                mma16816(O[0][n], phi[0], b0, b1);
                mma16816(O[0][n], plo[0], b0, b1);
                mma16816(O[1][n], phi[1], b0, b1);
                mma16816(O[1][n], plo[1], b0, b1);
            }
        }

        if (kt < 63) CP_WAIT0();
        __syncthreads();
    }

    // ---- epilogue 1: l-reduce, normalize (2^-16 shift cancels), fq z, stage ----
    const float si = s_in_p[0];
    const float so = s_out_p[0];
    float* zs = (float*)(sm + SM_QHI);
#pragma unroll
    for (int m = 0; m < 2; m++)
#pragma unroll
        for (int h = 0; h < 2; h++) {
            float lv = l_acc[m][h];
            lv += __shfl_xor_sync(0xffffffffu, lv, 1);
            lv += __shfl_xor_sync(0xffffffffu, lv, 2);
            float inv = 1.0f / lv;
            int row = q0 + m * 16 + (lane >> 2) + h * 8;
#pragma unroll
            for (int n = 0; n < 4; n++) {
                float z0 = O[m][n][h * 2 + 0] * inv;
                float z1 = O[m][n][h * 2 + 1] * inv;
                float r0 = fminf(fmaxf(rintf(z0 / si), -128.f), 127.f) * si;
                float r1 = fminf(fmaxf(rintf(z1 / si), -128.f), 127.f) * si;
                float2 u; u.x = r0; u.y = r1;
                *(float2*)(zs + row * 34 + n * 8 + (lane & 3) * 2) = u;
            }
        }
    __syncthreads();

    // ---- epilogue 2: output projection + residual + out fq (thread = pixel) ----
    {
        ull zp[16];
#pragma unroll
        for (int j = 0; j < 16; j++)
            zp[j] = pack2(zs[t * 34 + 2 * j], zs[t * 34 + 2 * j + 1]);
        const float* wsp = (const float*)(sm + SM_WP);
        const float* bps = (const float*)(sm + SM_BP);
        const float* xqb = g_xq + ((size_t)b * CC) * NN + qt * 256 + t;
        float* ob = out + ((size_t)b * CC) * NN + qt * 256 + t;
#pragma unroll
        for (int c0 = 0; c0 < CC; c0 += 16) {
            float xv[16];
#pragma unroll
            for (int u = 0; u < 16; u++) xv[u] = xqb[(size_t)(c0 + u) * NN];
#pragma unroll
            for (int u = 0; u < 16; u++) {
                int c = c0 + u;
                ull a0 = 0ull, a1 = 0ull;
                const ulonglong2* wr = (const ulonglong2*)(wsp + c * HC);
#pragma unroll
                for (int j = 0; j < 8; j++) {
                    ulonglong2 uu = wr[j];
                    fma2(a0, zp[2 * j], uu.x);
                    fma2(a1, zp[2 * j + 1], uu.y);
                }
                float f0, f1, f2, f3;
                unpack2(a0, f0, f1);
                unpack2(a1, f2, f3);
                float val = xv[u] + (f0 + f1) + (f2 + f3) + bps[c];
                float r = rintf(val / so);
                r = fminf(fmaxf(r, -128.f), 127.f);
                ob[(size_t)c * NN] = r * so;
            }
        }
    }
}

// ---------------- launch ----------------------------------------------------------
extern "C" void kernel_launch(void* const* d_in, const int* in_sizes, int n_in,
                              void* d_out, int out_size) {
    const float* x     = (const float*)d_in[0];
    const float* wq    = (const float*)d_in[1];
    const float* bq    = (const float*)d_in[2];
    const float* wk    = (const float*)d_in[3];
    const float* bk    = (const float*)d_in[4];
    const float* wv    = (const float*)d_in[5];
    const float* bv    = (const float*)d_in[6];
    const float* wp    = (const float*)d_in[7];
    const float* bp    = (const float*)d_in[8];
    const float* s_in  = (const float*)d_in[9];
    const float* s_out = (const float*)d_in[10];
    float* out = (float*)d_out;

    const int smemB = (CC * 128 + CC * 96) * 4;
    cudaFuncSetAttribute(k_xq_qkv, cudaFuncAttributeMaxDynamicSharedMemorySize, smemB);
    cudaFuncSetAttribute(k_attn, cudaFuncAttributeMaxDynamicSharedMemorySize, ATTN_SMEM);

    k_xq_qkv<<<dim3(32, 8), 128, smemB>>>(x, wq, wk, wv, bq, bk, bv, s_in);
    k_attn<<<dim3(16, 8), 256, ATTN_SMEM>>>(wp, bp, s_in, s_out, out);
}

// round 13
// speedup vs baseline: 1.5612x; 1.2020x over previous
#include <cuda_runtime.h>
#include <cuda_fp16.h>
#include <math.h>
#include <stdint.h>

typedef unsigned long long ull;

// ---------------- f32x2 packed-math helpers ------------------------------------
__device__ __forceinline__ ull pack2(float lo, float hi) {
    ull r; asm("mov.b64 %0, {%1, %2};" : "=l"(r) : "f"(lo), "f"(hi)); return r;
}
__device__ __forceinline__ void unpack2(ull v, float& lo, float& hi) {
    asm("mov.b64 {%0, %1}, %2;" : "=f"(lo), "=f"(hi) : "l"(v));
}
__device__ __forceinline__ void fma2(ull& d, ull a, ull b) {
    asm("fma.rn.f32x2 %0, %1, %2, %0;" : "+l"(d) : "l"(a), "l"(b));
}

// ---------------- fp16 / mma helpers ---------------------------------------------
__device__ __forceinline__ uint32_t packh(float lo, float hi) {  // {lo->low16, hi->high16}
    uint32_t r; asm("cvt.rn.f16x2.f32 %0, %1, %2;" : "=r"(r) : "f"(hi), "f"(lo)); return r;
}
__device__ __forceinline__ float loH(uint32_t u) {
    float f; asm("{.reg .f16 l,h; mov.b32 {l,h}, %1; cvt.f32.f16 %0, l;}" : "=f"(f) : "r"(u));
    return f;
}
__device__ __forceinline__ float hiH(uint32_t u) {
    float f; asm("{.reg .f16 l,h; mov.b32 {l,h}, %1; cvt.f32.f16 %0, h;}" : "=f"(f) : "r"(u));
    return f;
}
__device__ __forceinline__ float ex2f(float x) {
    float r; asm("ex2.approx.f32 %0, %1;" : "=f"(r) : "f"(x)); return r;
}

__device__ __forceinline__ uint32_t cvta_s(const void* p) {
    uint32_t a;
    asm("{ .reg .u64 t; cvta.to.shared.u64 t, %1; cvt.u32.u64 %0, t; }" : "=r"(a) : "l"(p));
    return a;
}
__device__ __forceinline__ void ldmx4(uint32_t* r, uint32_t a) {
    asm volatile("ldmatrix.sync.aligned.m8n8.x4.shared.b16 {%0,%1,%2,%3}, [%4];"
                 : "=r"(r[0]), "=r"(r[1]), "=r"(r[2]), "=r"(r[3]) : "r"(a));
}
__device__ __forceinline__ void mma16816(float* c, const uint32_t* a, uint32_t b0, uint32_t b1) {
    asm volatile(
        "mma.sync.aligned.m16n8k16.row.col.f32.f16.f16.f32 "
        "{%0,%1,%2,%3}, {%4,%5,%6,%7}, {%8,%9}, {%0,%1,%2,%3};"
        : "+f"(c[0]), "+f"(c[1]), "+f"(c[2]), "+f"(c[3])
        : "r"(a[0]), "r"(a[1]), "r"(a[2]), "r"(a[3]), "r"(b0), "r"(b1));
}
__device__ __forceinline__ void cpa16(uint32_t dst, const void* src) {
    asm volatile("cp.async.cg.shared.global [%0], [%1], 16;" :: "r"(dst), "l"(src) : "memory");
}
#define CP_COMMIT() asm volatile("cp.async.commit_group;" ::: "memory")
#define CP_WAIT0()  asm volatile("cp.async.wait_group 0;" ::: "memory")

// ---------------- problem constants -------------------------------------------
#define BB 8
#define CC 64
#define HC 32
#define NN 4096
#define LOG2E 1.4426950408889634f
#define PSHIFT 16.0f   // P' = 2^(S*log2e - 16); cancels exactly in O/l

// ---------------- device scratch -----------------------------------------------
__device__ __align__(16) float g_xq[BB * CC * NN];            // [b][c][n]
__device__ __align__(16) unsigned short g_qhi[BB * NN * HC];  // fp16(q*log2e) hi
__device__ __align__(16) unsigned short g_qlo[BB * NN * HC];  // fp16 residual
__device__ __align__(16) unsigned short g_khi[BB * NN * HC];  // fp16 K
__device__ __align__(16) unsigned short g_vthi[BB * HC * NN]; // fp16 V^T [b][d][n]

// ---------------- kernel B: weight quant + x fake-quant + fused QKV -------------
__global__ void __launch_bounds__(128) k_xq_qkv(const float* __restrict__ x,
                                                const float* __restrict__ wq,
                                                const float* __restrict__ wk,
                                                const float* __restrict__ wv,
                                                const float* __restrict__ bq,
                                                const float* __restrict__ bk,
                                                const float* __restrict__ bv,
                                                const float* __restrict__ s_in_p) {
    extern __shared__ float smB[];
    float* xs = smB;                 // [64][128]
    float* ws = smB + CC * 128;      // [64][96]
    __shared__ float redw[12];
    const int t = threadIdx.x;
    const int b = blockIdx.y;
    const int n0 = blockIdx.x * 128;
    const float si = s_in_p[0];

    // ---- x fake-quant into smem + global ----
    const float* xb = x + ((size_t)b * CC) * NN + n0;
    float* xqb = g_xq + ((size_t)b * CC) * NN + n0;
#pragma unroll 4
    for (int c = 0; c < CC; c++) {
        float v = xb[c * NN + t];
        float r = rintf(v / si);
        r = fminf(fmaxf(r, -128.f), 127.f);
        float q = r * si;
        xqb[c * NN + t] = q;
        xs[c * 128 + t] = q;
    }

    // ---- per-tensor weight max-abs (redundant per block; deterministic) ----
    float mx0 = 0.f, mx1 = 0.f, mx2 = 0.f;
    for (int i = t; i < CC * HC; i += 128) {
        mx0 = fmaxf(mx0, fabsf(wq[i]));
        mx1 = fmaxf(mx1, fabsf(wk[i]));
        mx2 = fmaxf(mx2, fabsf(wv[i]));
    }
#pragma unroll
    for (int s = 16; s; s >>= 1) {
        mx0 = fmaxf(mx0, __shfl_xor_sync(0xffffffffu, mx0, s));
        mx1 = fmaxf(mx1, __shfl_xor_sync(0xffffffffu, mx1, s));
        mx2 = fmaxf(mx2, __shfl_xor_sync(0xffffffffu, mx2, s));
    }
    if ((t & 31) == 0) {
        redw[t >> 5] = mx0; redw[4 + (t >> 5)] = mx1; redw[8 + (t >> 5)] = mx2;
    }
    __syncthreads();
    float s0 = fmaxf(fmaxf(redw[0], redw[1]), fmaxf(redw[2], redw[3])) / 127.f;
    float s1 = fmaxf(fmaxf(redw[4], redw[5]), fmaxf(redw[6], redw[7])) / 127.f;
    float s2 = fmaxf(fmaxf(redw[8], redw[9]), fmaxf(redw[10], redw[11])) / 127.f;
    // quantize weights into transposed smem [c][96]
    for (int i = t; i < CC * HC; i += 128) {
        int hc = i >> 6, c = i & 63;
        ws[c * 96 + hc]      = fminf(fmaxf(rintf(wq[i] / s0), -127.f), 127.f) * s0;
        ws[c * 96 + 32 + hc] = fminf(fmaxf(rintf(wk[i] / s1), -127.f), 127.f) * s1;
        ws[c * 96 + 64 + hc] = fminf(fmaxf(rintf(wv[i] / s2), -127.f), 127.f) * s2;
    }
    __syncthreads();

    ull aq[16], ak[16], av[16];
#pragma unroll
    for (int h = 0; h < 16; h++) {
        aq[h] = pack2(bq[2 * h], bq[2 * h + 1]);
        ak[h] = pack2(bk[2 * h], bk[2 * h + 1]);
        av[h] = pack2(bv[2 * h], bv[2 * h + 1]);
    }
#pragma unroll 2
    for (int c = 0; c < CC; c++) {
        float xv = xs[c * 128 + t];
        ull xp = pack2(xv, xv);
        const ulonglong2* wr = (const ulonglong2*)(ws + c * 96);
#pragma unroll
        for (int j = 0; j < 8; j++) {
            ulonglong2 u = wr[j];
            fma2(aq[2 * j], xp, u.x);
            fma2(aq[2 * j + 1], xp, u.y);
        }
#pragma unroll
        for (int j = 0; j < 8; j++) {
            ulonglong2 u = wr[8 + j];
            fma2(ak[2 * j], xp, u.x);
            fma2(ak[2 * j + 1], xp, u.y);
        }
#pragma unroll
        for (int j = 0; j < 8; j++) {
            ulonglong2 u = wr[16 + j];
            fma2(av[2 * j], xp, u.x);
            fma2(av[2 * j + 1], xp, u.y);
        }
    }

    size_t bn = (size_t)b * NN + n0 + t;
    // Q scaled by log2e, fp16 hi + residual lo. K single fp16.
    uint32_t qh[16], ql[16], kh[16];
#pragma unroll
    for (int j = 0; j < 16; j++) {
        float f0, f1;
        unpack2(aq[j], f0, f1);
        f0 *= LOG2E; f1 *= LOG2E;
        uint32_t u = packh(f0, f1);
        qh[j] = u;
        ql[j] = packh(f0 - loH(u), f1 - hiH(u));
        unpack2(ak[j], f0, f1);
        kh[j] = packh(f0, f1);
    }
    uint4* qhp = (uint4*)(g_qhi + bn * HC);
    uint4* qlp = (uint4*)(g_qlo + bn * HC);
    uint4* khp = (uint4*)(g_khi + bn * HC);
#pragma unroll
    for (int c4 = 0; c4 < 4; c4++) {
        uint4 u;
        u.x = qh[4 * c4]; u.y = qh[4 * c4 + 1]; u.z = qh[4 * c4 + 2]; u.w = qh[4 * c4 + 3];
        qhp[c4] = u;
        u.x = ql[4 * c4]; u.y = ql[4 * c4 + 1]; u.z = ql[4 * c4 + 2]; u.w = ql[4 * c4 + 3];
        qlp[c4] = u;
        u.x = kh[4 * c4]; u.y = kh[4 * c4 + 1]; u.z = kh[4 * c4 + 2]; u.w = kh[4 * c4 + 3];
        khp[c4] = u;
    }
    // V transposed, single fp16
    unsigned short* vh = g_vthi + (size_t)b * HC * NN + n0 + t;
#pragma unroll
    for (int j = 0; j < 16; j++) {
        float f0, f1;
        unpack2(av[j], f0, f1);
        uint32_t u = packh(f0, f1);
        vh[(size_t)(2 * j) * NN] = (unsigned short)(u & 0xffffu);
        vh[(size_t)(2 * j + 1) * NN] = (unsigned short)(u >> 16);
    }
}

// ---------------- kernel C: HMMA flash attention + fused proj ---------------------
// grid (16, 8) = (q-tile 256, batch), 256 threads / 8 warps, 32 q-rows per warp.
// FP16 scheme: S = (Qhi+Qlo)*Kfp16 (2 MMA), O = Pfp16*Vfp16 (1 MMA)
// -> 192 MMA/SMSP/kt. P exponent-shifted by 2^-16 (cancels exactly in O/l).
#define SM_QHI 0            // 256 rows x 80B
#define SM_QLO 20480
#define SM_K   40960        // + buf*5120 : K 64x80
#define SM_V   51200        // + buf*4608 : V 32x144
#define SM_WP  60416        // wp quantized 64x32 f32
#define SM_BP  68608        // bp 64 f32
#define ATTN_SMEM 68864
// epilogue zs (256x34 f32 = 34816B) reuses the Q region

__global__ void __launch_bounds__(256, 1) k_attn(const float* __restrict__ wp,
                                                 const float* __restrict__ bp,
                                                 const float* __restrict__ s_in_p,
                                                 const float* __restrict__ s_out_p,
                                                 float* __restrict__ out) {
    extern __shared__ char sm[];
    __shared__ float redp[8];
    uint32_t sb = cvta_s(sm);
    const int t = threadIdx.x;
    const int w = t >> 5, lane = t & 31;
    const int b = blockIdx.y, qt = blockIdx.x;
    const int q0 = w * 32;

    const char* pkhi = (const char*)g_khi + (size_t)b * NN * 64;
    const char* pvhi = (const char*)g_vthi + (size_t)b * HC * (NN * 2);

    // staging: K 256 + V 256 = 512 cp.async of 16B; 256 threads x 2
    auto stageKV = [&](int kt) {
        uint32_t kb = sb + SM_K + (kt & 1) * 5120;
        uint32_t vb = sb + SM_V + (kt & 1) * 4608;
#pragma unroll
        for (int i = 0; i < 2; i++) {
            int idx = t + i * 256;
            if (idx < 256) {
                int row = idx >> 2, ch = idx & 3;
                cpa16(kb + row * 80 + ch * 16,
                      pkhi + (size_t)(kt * 64 + row) * 64 + ch * 16);
            } else {
                int rem = idx & 255;
                int d = rem >> 3, ch = rem & 7;
                cpa16(vb + d * 144 + ch * 16,
                      pvhi + (size_t)d * (NN * 2) + kt * 128 + ch * 16);
            }
        }
    };

    // ---- prologue: stage Q + KV(0); quantize wp while cp.async flies ----
    {
        const char* pqhi = (const char*)g_qhi + (size_t)b * NN * 64;
        const char* pqlo = (const char*)g_qlo + (size_t)b * NN * 64;
#pragma unroll
        for (int i = 0; i < 8; i++) {
            int idx = t + i * 256;
            int part = idx >> 10, rem = idx & 1023;
            int row = rem >> 2, ch = rem & 3;
            const char* src = (part ? pqlo : pqhi) + (size_t)(qt * 256 + row) * 64 + ch * 16;
            cpa16(sb + SM_QHI + part * 20480 + row * 80 + ch * 16, src);
        }
    }
    stageKV(0);
    CP_COMMIT();
    {
        float mxp = 0.f;
        for (int i = t; i < CC * HC; i += 256) mxp = fmaxf(mxp, fabsf(wp[i]));
#pragma unroll
        for (int s = 16; s; s >>= 1) mxp = fmaxf(mxp, __shfl_xor_sync(0xffffffffu, mxp, s));
        if (lane == 0) redp[w] = mxp;
        __syncthreads();
        float sp = fmaxf(fmaxf(fmaxf(redp[0], redp[1]), fmaxf(redp[2], redp[3])),
                         fmaxf(fmaxf(redp[4], redp[5]), fmaxf(redp[6], redp[7]))) / 127.f;
        float* wsp = (float*)(sm + SM_WP);
        for (int i = t; i < CC * HC; i += 256)
            wsp[i] = fminf(fmaxf(rintf(wp[i] / sp), -127.f), 127.f) * sp;
        if (t < CC) ((float*)(sm + SM_BP))[t] = bp[t];
    }
    CP_WAIT0();
    __syncthreads();

    // Q fragments (2 m-tiles x 2 k16 chunks, hi + lo) via ldmatrix.x4
    uint32_t qfh[2][2][4], qfl[2][2][4];
#pragma unroll
    for (int m = 0; m < 2; m++) {
        uint32_t qa = sb + SM_QHI +
            (uint32_t)((q0 + m * 16 + (lane & 7) + ((lane >> 3) & 1) * 8) * 80 +
                       ((lane >> 4) & 1) * 16);
        ldmx4(qfh[m][0], qa);
        ldmx4(qfh[m][1], qa + 32);
        ldmx4(qfl[m][0], qa + 20480);
        ldmx4(qfl[m][1], qa + 20480 + 32);
    }

    float O[2][4][4];
    float l_acc[2][2] = {{0.f, 0.f}, {0.f, 0.f}};
#pragma unroll
    for (int m = 0; m < 2; m++)
#pragma unroll
        for (int n = 0; n < 4; n++)
#pragma unroll
            for (int i = 0; i < 4; i++) O[m][n][i] = 0.f;

    // ---- main loop: 64 tiles of 64 keys ----
    for (int kt = 0; kt < 64; kt++) {
        uint32_t kb = sb + SM_K + (kt & 1) * 5120;
        uint32_t vb = sb + SM_V + (kt & 1) * 4608;
        if (kt < 63) { stageKV(kt + 1); CP_COMMIT(); }

        const uint32_t ka0 = kb + (uint32_t)((lane & 7) * 80 + (lane >> 3) * 16);

        // S = (Qhi + Qlo) * K, single-fp16 K, depth-1 K-fragment prefetch
        float S[2][8][4];
#pragma unroll
        for (int m = 0; m < 2; m++)
#pragma unroll
            for (int j = 0; j < 8; j++)
#pragma unroll
                for (int i = 0; i < 4; i++) S[m][j][i] = 0.f;

        uint32_t kf[2][4];
        ldmx4(kf[0], ka0);
#pragma unroll
        for (int j = 0; j < 8; j++) {
            const int cur = j & 1, nxt = cur ^ 1;
            if (j < 7) ldmx4(kf[nxt], ka0 + (uint32_t)((j + 1) * 8 * 80));
            // ks = 0 (dims 0-15)
            mma16816(S[0][j], qfh[0][0], kf[cur][0], kf[cur][1]);
            mma16816(S[0][j], qfl[0][0], kf[cur][0], kf[cur][1]);
            mma16816(S[1][j], qfh[1][0], kf[cur][0], kf[cur][1]);
            mma16816(S[1][j], qfl[1][0], kf[cur][0], kf[cur][1]);
            // ks = 1 (dims 16-31)
            mma16816(S[0][j], qfh[0][1], kf[cur][2], kf[cur][3]);
            mma16816(S[0][j], qfl[0][1], kf[cur][2], kf[cur][3]);
            mma16816(S[1][j], qfh[1][1], kf[cur][2], kf[cur][3]);
            mma16816(S[1][j], qfl[1][1], kf[cur][2], kf[cur][3]);
        }

        const uint32_t va0 = vb +
            (uint32_t)((((lane >> 4) & 1) * 8 + (lane & 7)) * 144 + ((lane >> 3) & 1) * 16);

        // PV in 16-key chunks: single-fp16 P (2^-16 shifted), V loads hoisted
#pragma unroll
        for (int kk = 0; kk < 4; kk++) {
            uint32_t vf[8];
            ldmx4(vf, va0 + kk * 32);                 // n 0-1
            ldmx4(vf + 4, va0 + kk * 32 + 16 * 144);  // n 2-3

            uint32_t phi[2][4];
#pragma unroll
            for (int m = 0; m < 2; m++) {
                const int j0 = 2 * kk, j1 = 2 * kk + 1;
                float e0 = ex2f(S[m][j0][0] - PSHIFT);
                float e1 = ex2f(S[m][j0][1] - PSHIFT);
                float e2 = ex2f(S[m][j0][2] - PSHIFT);
                float e3 = ex2f(S[m][j0][3] - PSHIFT);
                float e4 = ex2f(S[m][j1][0] - PSHIFT);
                float e5 = ex2f(S[m][j1][1] - PSHIFT);
                float e6 = ex2f(S[m][j1][2] - PSHIFT);
                float e7 = ex2f(S[m][j1][3] - PSHIFT);
                l_acc[m][0] += (e0 + e1) + (e4 + e5);
                l_acc[m][1] += (e2 + e3) + (e6 + e7);
                phi[m][0] = packh(e0, e1);
                phi[m][1] = packh(e2, e3);
                phi[m][2] = packh(e4, e5);
                phi[m][3] = packh(e6, e7);
            }
#pragma unroll
            for (int n = 0; n < 4; n++) {
                uint32_t b0 = vf[2 * n], b1 = vf[2 * n + 1];
                mma16816(O[0][n], phi[0], b0, b1);
                mma16816(O[1][n], phi[1], b0, b1);
            }
        }

        if (kt < 63) CP_WAIT0();
        __syncthreads();
    }

    // ---- epilogue 1: l-reduce, normalize (2^-16 shift cancels), fq z, stage ----
    const float si = s_in_p[0];
    const float so = s_out_p[0];
    float* zs = (float*)(sm + SM_QHI);
#pragma unroll
    for (int m = 0; m < 2; m++)
#pragma unroll
        for (int h = 0; h < 2; h++) {
            float lv = l_acc[m][h];
            lv += __shfl_xor_sync(0xffffffffu, lv, 1);
            lv += __shfl_xor_sync(0xffffffffu, lv, 2);
            float inv = 1.0f / lv;
            int row = q0 + m * 16 + (lane >> 2) + h * 8;
#pragma unroll
            for (int n = 0; n < 4; n++) {
                float z0 = O[m][n][h * 2 + 0] * inv;
                float z1 = O[m][n][h * 2 + 1] * inv;
                float r0 = fminf(fmaxf(rintf(z0 / si), -128.f), 127.f) * si;
                float r1 = fminf(fmaxf(rintf(z1 / si), -128.f), 127.f) * si;
                float2 u; u.x = r0; u.y = r1;
                *(float2*)(zs + row * 34 + n * 8 + (lane & 3) * 2) = u;
            }
        }
    __syncthreads();

    // ---- epilogue 2: output projection + residual + out fq (thread = pixel) ----
    {
        ull zp[16];
#pragma unroll
        for (int j = 0; j < 16; j++)
            zp[j] = pack2(zs[t * 34 + 2 * j], zs[t * 34 + 2 * j + 1]);
        const float* wsp = (const float*)(sm + SM_WP);
        const float* bps = (const float*)(sm + SM_BP);
        const float* xqb = g_xq + ((size_t)b * CC) * NN + qt * 256 + t;
        float* ob = out + ((size_t)b * CC) * NN + qt * 256 + t;
#pragma unroll
        for (int c0 = 0; c0 < CC; c0 += 16) {
            float xv[16];
#pragma unroll
            for (int u = 0; u < 16; u++) xv[u] = xqb[(size_t)(c0 + u) * NN];
#pragma unroll
            for (int u = 0; u < 16; u++) {
                int c = c0 + u;
                ull a0 = 0ull, a1 = 0ull;
                const ulonglong2* wr = (const ulonglong2*)(wsp + c * HC);
#pragma unroll
                for (int j = 0; j < 8; j++) {
                    ulonglong2 uu = wr[j];
                    fma2(a0, zp[2 * j], uu.x);
                    fma2(a1, zp[2 * j + 1], uu.y);
                }
                float f0, f1, f2, f3;
                unpack2(a0, f0, f1);
                unpack2(a1, f2, f3);
                float val = xv[u] + (f0 + f1) + (f2 + f3) + bps[c];
                float r = rintf(val / so);
                r = fminf(fmaxf(r, -128.f), 127.f);
                ob[(size_t)c * NN] = r * so;
            }
        }
    }
}

// ---------------- launch ----------------------------------------------------------
extern "C" void kernel_launch(void* const* d_in, const int* in_sizes, int n_in,
                              void* d_out, int out_size) {
    const float* x     = (const float*)d_in[0];
    const float* wq    = (const float*)d_in[1];
    const float* bq    = (const float*)d_in[2];
    const float* wk    = (const float*)d_in[3];
    const float* bk    = (const float*)d_in[4];
    const float* wv    = (const float*)d_in[5];
    const float* bv    = (const float*)d_in[6];
    const float* wp    = (const float*)d_in[7];
    const float* bp    = (const float*)d_in[8];
    const float* s_in  = (const float*)d_in[9];
    const float* s_out = (const float*)d_in[10];
    float* out = (float*)d_out;

    const int smemB = (CC * 128 + CC * 96) * 4;
    cudaFuncSetAttribute(k_xq_qkv, cudaFuncAttributeMaxDynamicSharedMemorySize, smemB);
    cudaFuncSetAttribute(k_attn, cudaFuncAttributeMaxDynamicSharedMemorySize, ATTN_SMEM);

    k_xq_qkv<<<dim3(32, 8), 128, smemB>>>(x, wq, wk, wv, bq, bk, bv, s_in);
    k_attn<<<dim3(16, 8), 256, ATTN_SMEM>>>(wp, bp, s_in, s_out, out);
}

// round 14
// speedup vs baseline: 1.6991x; 1.0883x over previous
#include <cuda_runtime.h>
#include <cuda_fp16.h>
#include <math.h>
#include <stdint.h>

typedef unsigned long long ull;

// ---------------- f32x2 packed-math helpers ------------------------------------
__device__ __forceinline__ ull pack2(float lo, float hi) {
    ull r; asm("mov.b64 %0, {%1, %2};" : "=l"(r) : "f"(lo), "f"(hi)); return r;
}
__device__ __forceinline__ void unpack2(ull v, float& lo, float& hi) {
    asm("mov.b64 {%0, %1}, %2;" : "=f"(lo), "=f"(hi) : "l"(v));
}
__device__ __forceinline__ void fma2(ull& d, ull a, ull b) {
    asm("fma.rn.f32x2 %0, %1, %2, %0;" : "+l"(d) : "l"(a), "l"(b));
}

// ---------------- fp16 / mma helpers ---------------------------------------------
__device__ __forceinline__ uint32_t packh(float lo, float hi) {  // {lo->low16, hi->high16}
    uint32_t r; asm("cvt.rn.f16x2.f32 %0, %1, %2;" : "=r"(r) : "f"(hi), "f"(lo)); return r;
}
__device__ __forceinline__ float loH(uint32_t u) {
    float f; asm("{.reg .f16 l,h; mov.b32 {l,h}, %1; cvt.f32.f16 %0, l;}" : "=f"(f) : "r"(u));
    return f;
}
__device__ __forceinline__ float hiH(uint32_t u) {
    float f; asm("{.reg .f16 l,h; mov.b32 {l,h}, %1; cvt.f32.f16 %0, h;}" : "=f"(f) : "r"(u));
    return f;
}
__device__ __forceinline__ float ex2f(float x) {
    float r; asm("ex2.approx.f32 %0, %1;" : "=f"(r) : "f"(x)); return r;
}

__device__ __forceinline__ uint32_t cvta_s(const void* p) {
    uint32_t a;
    asm("{ .reg .u64 t; cvta.to.shared.u64 t, %1; cvt.u32.u64 %0, t; }" : "=r"(a) : "l"(p));
    return a;
}
__device__ __forceinline__ void ldmx4(uint32_t* r, uint32_t a) {
    asm volatile("ldmatrix.sync.aligned.m8n8.x4.shared.b16 {%0,%1,%2,%3}, [%4];"
                 : "=r"(r[0]), "=r"(r[1]), "=r"(r[2]), "=r"(r[3]) : "r"(a));
}
__device__ __forceinline__ void mma16816(float* c, const uint32_t* a, uint32_t b0, uint32_t b1) {
    asm volatile(
        "mma.sync.aligned.m16n8k16.row.col.f32.f16.f16.f32 "
        "{%0,%1,%2,%3}, {%4,%5,%6,%7}, {%8,%9}, {%0,%1,%2,%3};"
        : "+f"(c[0]), "+f"(c[1]), "+f"(c[2]), "+f"(c[3])
        : "r"(a[0]), "r"(a[1]), "r"(a[2]), "r"(a[3]), "r"(b0), "r"(b1));
}
__device__ __forceinline__ void cpa16(uint32_t dst, const void* src) {
    asm volatile("cp.async.cg.shared.global [%0], [%1], 16;" :: "r"(dst), "l"(src) : "memory");
}
#define CP_COMMIT() asm volatile("cp.async.commit_group;" ::: "memory")
#define CP_WAIT0()  asm volatile("cp.async.wait_group 0;" ::: "memory")

// ---------------- problem constants -------------------------------------------
#define BB 8
#define CC 64
#define HC 32
#define NN 4096
#define LOG2E 1.4426950408889634f
#define PSHIFT 16.0f   // P' = 2^(S*log2e - 16); cancels exactly in O/l

// ---------------- device scratch -----------------------------------------------
__device__ __align__(16) float g_xq[BB * CC * NN];            // [b][c][n]
__device__ __align__(16) unsigned short g_qhi[BB * NN * HC];  // fp16(q*log2e) hi
__device__ __align__(16) unsigned short g_qlo[BB * NN * HC];  // fp16 residual
__device__ __align__(16) unsigned short g_khi[BB * NN * HC];  // fp16 K
__device__ __align__(16) unsigned short g_vthi[BB * HC * NN]; // fp16 V^T [b][d][n]

// ---------------- kernel B: weight quant + x fake-quant + fused QKV -------------
// grid (16, 8) = 128 blocks, 512 threads, 256 pixels/block.
// Thread (px, h): pixel px, computes Q/K/V channels [16h, 16h+16).
// Same per-channel fma2 accumulation order as before -> bitwise-identical QKV.
__global__ void __launch_bounds__(512) k_xq_qkv(const float* __restrict__ x,
                                                const float* __restrict__ wq,
                                                const float* __restrict__ wk,
                                                const float* __restrict__ wv,
                                                const float* __restrict__ bq,
                                                const float* __restrict__ bk,
                                                const float* __restrict__ bv,
                                                const float* __restrict__ s_in_p) {
    extern __shared__ float smB[];
    float* xs = smB;                  // [64][256]
    float* ws = smB + CC * 256;       // [64][96]
    __shared__ float redw[48];
    const int t = threadIdx.x;
    const int px = t & 255, h = t >> 8;
    const int b = blockIdx.y;
    const int n0 = blockIdx.x * 256;
    const float si = s_in_p[0];

    // ---- x fake-quant into smem + global ----
    const float* xb = x + ((size_t)b * CC) * NN + n0;
    float* xqb = g_xq + ((size_t)b * CC) * NN + n0;
#pragma unroll 4
    for (int idx = t; idx < CC * 256; idx += 512) {
        int c = idx >> 8, p = idx & 255;
        float v = xb[c * NN + p];
        float r = rintf(v / si);
        r = fminf(fmaxf(r, -128.f), 127.f);
        float q = r * si;
        xqb[c * NN + p] = q;
        xs[idx] = q;
    }

    // ---- per-tensor weight max-abs (redundant per block; deterministic) ----
    float mx0 = 0.f, mx1 = 0.f, mx2 = 0.f;
    for (int i = t; i < CC * HC; i += 512) {
        mx0 = fmaxf(mx0, fabsf(wq[i]));
        mx1 = fmaxf(mx1, fabsf(wk[i]));
        mx2 = fmaxf(mx2, fabsf(wv[i]));
    }
#pragma unroll
    for (int s = 16; s; s >>= 1) {
        mx0 = fmaxf(mx0, __shfl_xor_sync(0xffffffffu, mx0, s));
        mx1 = fmaxf(mx1, __shfl_xor_sync(0xffffffffu, mx1, s));
        mx2 = fmaxf(mx2, __shfl_xor_sync(0xffffffffu, mx2, s));
    }
    const int w16 = t >> 5;
    if ((t & 31) == 0) {
        redw[w16] = mx0; redw[16 + w16] = mx1; redw[32 + w16] = mx2;
    }
    __syncthreads();
    float s0 = 0.f, s1 = 0.f, s2 = 0.f;
#pragma unroll
    for (int i = 0; i < 16; i++) {
        s0 = fmaxf(s0, redw[i]);
        s1 = fmaxf(s1, redw[16 + i]);
        s2 = fmaxf(s2, redw[32 + i]);
    }
    s0 /= 127.f; s1 /= 127.f; s2 /= 127.f;
    // quantize weights into transposed smem [c][96]
    for (int i = t; i < CC * HC; i += 512) {
        int hc = i >> 6, c = i & 63;
        ws[c * 96 + hc]      = fminf(fmaxf(rintf(wq[i] / s0), -127.f), 127.f) * s0;
        ws[c * 96 + 32 + hc] = fminf(fmaxf(rintf(wk[i] / s1), -127.f), 127.f) * s1;
        ws[c * 96 + 64 + hc] = fminf(fmaxf(rintf(wv[i] / s2), -127.f), 127.f) * s2;
    }
    __syncthreads();

    // ---- accumulators: 8 ull each for Q/K/V channels [16h, 16h+16) ----
    ull aq[8], ak[8], av[8];
#pragma unroll
    for (int j = 0; j < 8; j++) {
        aq[j] = pack2(bq[16 * h + 2 * j], bq[16 * h + 2 * j + 1]);
        ak[j] = pack2(bk[16 * h + 2 * j], bk[16 * h + 2 * j + 1]);
        av[j] = pack2(bv[16 * h + 2 * j], bv[16 * h + 2 * j + 1]);
    }
#pragma unroll 2
    for (int c = 0; c < CC; c++) {
        float xv = xs[c * 256 + px];
        ull xp = pack2(xv, xv);
        const ulonglong2* wr = (const ulonglong2*)(ws + c * 96);
#pragma unroll
        for (int j = 0; j < 4; j++) {
            ulonglong2 u = wr[4 * h + j];
            fma2(aq[2 * j], xp, u.x);
            fma2(aq[2 * j + 1], xp, u.y);
        }
#pragma unroll
        for (int j = 0; j < 4; j++) {
            ulonglong2 u = wr[8 + 4 * h + j];
            fma2(ak[2 * j], xp, u.x);
            fma2(ak[2 * j + 1], xp, u.y);
        }
#pragma unroll
        for (int j = 0; j < 4; j++) {
            ulonglong2 u = wr[16 + 4 * h + j];
            fma2(av[2 * j], xp, u.x);
            fma2(av[2 * j + 1], xp, u.y);
        }
    }

    size_t bn = (size_t)b * NN + n0 + px;
    // Q scaled by log2e, fp16 hi + residual lo. K single fp16.
    uint32_t qh[8], ql[8], kh[8];
#pragma unroll
    for (int j = 0; j < 8; j++) {
        float f0, f1;
        unpack2(aq[j], f0, f1);
        f0 *= LOG2E; f1 *= LOG2E;
        uint32_t u = packh(f0, f1);
        qh[j] = u;
        ql[j] = packh(f0 - loH(u), f1 - hiH(u));
        unpack2(ak[j], f0, f1);
        kh[j] = packh(f0, f1);
    }
    uint4* qhp = (uint4*)(g_qhi + bn * HC + 16 * h);
    uint4* qlp = (uint4*)(g_qlo + bn * HC + 16 * h);
    uint4* khp = (uint4*)(g_khi + bn * HC + 16 * h);
#pragma unroll
    for (int c4 = 0; c4 < 2; c4++) {
        uint4 u;
        u.x = qh[4 * c4]; u.y = qh[4 * c4 + 1]; u.z = qh[4 * c4 + 2]; u.w = qh[4 * c4 + 3];
        qhp[c4] = u;
        u.x = ql[4 * c4]; u.y = ql[4 * c4 + 1]; u.z = ql[4 * c4 + 2]; u.w = ql[4 * c4 + 3];
        qlp[c4] = u;
        u.x = kh[4 * c4]; u.y = kh[4 * c4 + 1]; u.z = kh[4 * c4 + 2]; u.w = kh[4 * c4 + 3];
        khp[c4] = u;
    }
    // V transposed, single fp16, channels [16h, 16h+16)
    unsigned short* vh = g_vthi + ((size_t)b * HC + 16 * h) * NN + n0 + px;
#pragma unroll
    for (int j = 0; j < 8; j++) {
        float f0, f1;
        unpack2(av[j], f0, f1);
        uint32_t u = packh(f0, f1);
        vh[(size_t)(2 * j) * NN] = (unsigned short)(u & 0xffffu);
        vh[(size_t)(2 * j + 1) * NN] = (unsigned short)(u >> 16);
    }
}

// ---------------- kernel C: HMMA flash attention + fused proj ---------------------
// grid (16, 8) = (q-tile 256, batch), 256 threads / 8 warps, 32 q-rows per warp.
// FP16 scheme: S = (Qhi+Qlo)*Kfp16 (2 MMA), O = Pfp16*Vfp16 (1 MMA)
// -> 192 MMA/SMSP/kt. P exponent-shifted by 2^-16 (cancels exactly in O/l).
#define SM_QHI 0            // 256 rows x 80B
#define SM_QLO 20480
#define SM_K   40960        // + buf*5120 : K 64x80
#define SM_V   51200        // + buf*4608 : V 32x144
#define SM_WP  60416        // wp quantized 64x32 f32
#define SM_BP  68608        // bp 64 f32
#define ATTN_SMEM 68864
// epilogue zs (256x34 f32 = 34816B) reuses the Q region

__global__ void __launch_bounds__(256, 1) k_attn(const float* __restrict__ wp,
                                                 const float* __restrict__ bp,
                                                 const float* __restrict__ s_in_p,
                                                 const float* __restrict__ s_out_p,
                                                 float* __restrict__ out) {
    extern __shared__ char sm[];
    __shared__ float redp[8];
    uint32_t sb = cvta_s(sm);
    const int t = threadIdx.x;
    const int w = t >> 5, lane = t & 31;
    const int b = blockIdx.y, qt = blockIdx.x;
    const int q0 = w * 32;

    const char* pkhi = (const char*)g_khi + (size_t)b * NN * 64;
    const char* pvhi = (const char*)g_vthi + (size_t)b * HC * (NN * 2);

    // staging: K 256 + V 256 = 512 cp.async of 16B; 256 threads x 2
    auto stageKV = [&](int kt) {
        uint32_t kb = sb + SM_K + (kt & 1) * 5120;
        uint32_t vb = sb + SM_V + (kt & 1) * 4608;
#pragma unroll
        for (int i = 0; i < 2; i++) {
            int idx = t + i * 256;
            if (idx < 256) {
                int row = idx >> 2, ch = idx & 3;
                cpa16(kb + row * 80 + ch * 16,
                      pkhi + (size_t)(kt * 64 + row) * 64 + ch * 16);
            } else {
                int rem = idx & 255;
                int d = rem >> 3, ch = rem & 7;
                cpa16(vb + d * 144 + ch * 16,
                      pvhi + (size_t)d * (NN * 2) + kt * 128 + ch * 16);
            }
        }
    };

    // ---- prologue: stage Q + KV(0); quantize wp while cp.async flies ----
    {
        const char* pqhi = (const char*)g_qhi + (size_t)b * NN * 64;
        const char* pqlo = (const char*)g_qlo + (size_t)b * NN * 64;
#pragma unroll
        for (int i = 0; i < 8; i++) {
            int idx = t + i * 256;
            int part = idx >> 10, rem = idx & 1023;
            int row = rem >> 2, ch = rem & 3;
            const char* src = (part ? pqlo : pqhi) + (size_t)(qt * 256 + row) * 64 + ch * 16;
            cpa16(sb + SM_QHI + part * 20480 + row * 80 + ch * 16, src);
        }
    }
    stageKV(0);
    CP_COMMIT();
    {
        float mxp = 0.f;
        for (int i = t; i < CC * HC; i += 256) mxp = fmaxf(mxp, fabsf(wp[i]));
#pragma unroll
        for (int s = 16; s; s >>= 1) mxp = fmaxf(mxp, __shfl_xor_sync(0xffffffffu, mxp, s));
        if (lane == 0) redp[w] = mxp;
        __syncthreads();
        float sp = fmaxf(fmaxf(fmaxf(redp[0], redp[1]), fmaxf(redp[2], redp[3])),
                         fmaxf(fmaxf(redp[4], redp[5]), fmaxf(redp[6], redp[7]))) / 127.f;
        float* wsp = (float*)(sm + SM_WP);
        for (int i = t; i < CC * HC; i += 256)
            wsp[i] = fminf(fmaxf(rintf(wp[i] / sp), -127.f), 127.f) * sp;
        if (t < CC) ((float*)(sm + SM_BP))[t] = bp[t];
    }
    CP_WAIT0();
    __syncthreads();

    // Q fragments (2 m-tiles x 2 k16 chunks, hi + lo) via ldmatrix.x4
    uint32_t qfh[2][2][4], qfl[2][2][4];
#pragma unroll
    for (int m = 0; m < 2; m++) {
        uint32_t qa = sb + SM_QHI +
            (uint32_t)((q0 + m * 16 + (lane & 7) + ((lane >> 3) & 1) * 8) * 80 +
                       ((lane >> 4) & 1) * 16);
        ldmx4(qfh[m][0], qa);
        ldmx4(qfh[m][1], qa + 32);
        ldmx4(qfl[m][0], qa + 20480);
        ldmx4(qfl[m][1], qa + 20480 + 32);
    }

    float O[2][4][4];
    float l_acc[2][2] = {{0.f, 0.f}, {0.f, 0.f}};
#pragma unroll
    for (int m = 0; m < 2; m++)
#pragma unroll
        for (int n = 0; n < 4; n++)
#pragma unroll
            for (int i = 0; i < 4; i++) O[m][n][i] = 0.f;

    // ---- main loop: 64 tiles of 64 keys ----
    for (int kt = 0; kt < 64; kt++) {
        uint32_t kb = sb + SM_K + (kt & 1) * 5120;
        uint32_t vb = sb + SM_V + (kt & 1) * 4608;
        if (kt < 63) { stageKV(kt + 1); CP_COMMIT(); }

        const uint32_t ka0 = kb + (uint32_t)((lane & 7) * 80 + (lane >> 3) * 16);

        // S = (Qhi + Qlo) * K, single-fp16 K, depth-1 K-fragment prefetch
        float S[2][8][4];
#pragma unroll
        for (int m = 0; m < 2; m++)
#pragma unroll
            for (int j = 0; j < 8; j++)
#pragma unroll
                for (int i = 0; i < 4; i++) S[m][j][i] = 0.f;

        uint32_t kf[2][4];
        ldmx4(kf[0], ka0);
#pragma unroll
        for (int j = 0; j < 8; j++) {
            const int cur = j & 1, nxt = cur ^ 1;
            if (j < 7) ldmx4(kf[nxt], ka0 + (uint32_t)((j + 1) * 8 * 80));
            // ks = 0 (dims 0-15)
            mma16816(S[0][j], qfh[0][0], kf[cur][0], kf[cur][1]);
            mma16816(S[0][j], qfl[0][0], kf[cur][0], kf[cur][1]);
            mma16816(S[1][j], qfh[1][0], kf[cur][0], kf[cur][1]);
            mma16816(S[1][j], qfl[1][0], kf[cur][0], kf[cur][1]);
            // ks = 1 (dims 16-31)
            mma16816(S[0][j], qfh[0][1], kf[cur][2], kf[cur][3]);
            mma16816(S[0][j], qfl[0][1], kf[cur][2], kf[cur][3]);
            mma16816(S[1][j], qfh[1][1], kf[cur][2], kf[cur][3]);
            mma16816(S[1][j], qfl[1][1], kf[cur][2], kf[cur][3]);
        }

        const uint32_t va0 = vb +
            (uint32_t)((((lane >> 4) & 1) * 8 + (lane & 7)) * 144 + ((lane >> 3) & 1) * 16);

        // PV in 16-key chunks: single-fp16 P (2^-16 shifted), V loads hoisted
#pragma unroll
        for (int kk = 0; kk < 4; kk++) {
            uint32_t vf[8];
            ldmx4(vf, va0 + kk * 32);                 // n 0-1
            ldmx4(vf + 4, va0 + kk * 32 + 16 * 144);  // n 2-3

            uint32_t phi[2][4];
#pragma unroll
            for (int m = 0; m < 2; m++) {
                const int j0 = 2 * kk, j1 = 2 * kk + 1;
                float e0 = ex2f(S[m][j0][0] - PSHIFT);
                float e1 = ex2f(S[m][j0][1] - PSHIFT);
                float e2 = ex2f(S[m][j0][2] - PSHIFT);
                float e3 = ex2f(S[m][j0][3] - PSHIFT);
                float e4 = ex2f(S[m][j1][0] - PSHIFT);
                float e5 = ex2f(S[m][j1][1] - PSHIFT);
                float e6 = ex2f(S[m][j1][2] - PSHIFT);
                float e7 = ex2f(S[m][j1][3] - PSHIFT);
                l_acc[m][0] += (e0 + e1) + (e4 + e5);
                l_acc[m][1] += (e2 + e3) + (e6 + e7);
                phi[m][0] = packh(e0, e1);
                phi[m][1] = packh(e2, e3);
                phi[m][2] = packh(e4, e5);
                phi[m][3] = packh(e6, e7);
            }
#pragma unroll
            for (int n = 0; n < 4; n++) {
                uint32_t b0 = vf[2 * n], b1 = vf[2 * n + 1];
                mma16816(O[0][n], phi[0], b0, b1);
                mma16816(O[1][n], phi[1], b0, b1);
            }
        }

        if (kt < 63) CP_WAIT0();
        __syncthreads();
    }

    // ---- epilogue 1: l-reduce, normalize (2^-16 shift cancels), fq z, stage ----
    const float si = s_in_p[0];
    const float so = s_out_p[0];
    float* zs = (float*)(sm + SM_QHI);
#pragma unroll
    for (int m = 0; m < 2; m++)
#pragma unroll
        for (int h = 0; h < 2; h++) {
            float lv = l_acc[m][h];
            lv += __shfl_xor_sync(0xffffffffu, lv, 1);
            lv += __shfl_xor_sync(0xffffffffu, lv, 2);
            float inv = 1.0f / lv;
            int row = q0 + m * 16 + (lane >> 2) + h * 8;
#pragma unroll
            for (int n = 0; n < 4; n++) {
                float z0 = O[m][n][h * 2 + 0] * inv;
                float z1 = O[m][n][h * 2 + 1] * inv;
                float r0 = fminf(fmaxf(rintf(z0 / si), -128.f), 127.f) * si;
                float r1 = fminf(fmaxf(rintf(z1 / si), -128.f), 127.f) * si;
                float2 u; u.x = r0; u.y = r1;
                *(float2*)(zs + row * 34 + n * 8 + (lane & 3) * 2) = u;
            }
        }
    __syncthreads();

    // ---- epilogue 2: output projection + residual + out fq (thread = pixel) ----
    {
        ull zp[16];
#pragma unroll
        for (int j = 0; j < 16; j++)
            zp[j] = pack2(zs[t * 34 + 2 * j], zs[t * 34 + 2 * j + 1]);
        const float* wsp = (const float*)(sm + SM_WP);
        const float* bps = (const float*)(sm + SM_BP);
        const float* xqb = g_xq + ((size_t)b * CC) * NN + qt * 256 + t;
        float* ob = out + ((size_t)b * CC) * NN + qt * 256 + t;
#pragma unroll
        for (int c0 = 0; c0 < CC; c0 += 16) {
            float xv[16];
#pragma unroll
            for (int u = 0; u < 16; u++) xv[u] = xqb[(size_t)(c0 + u) * NN];
#pragma unroll
            for (int u = 0; u < 16; u++) {
                int c = c0 + u;
                ull a0 = 0ull, a1 = 0ull;
                const ulonglong2* wr = (const ulonglong2*)(wsp + c * HC);
#pragma unroll
                for (int j = 0; j < 8; j++) {
                    ulonglong2 uu = wr[j];
                    fma2(a0, zp[2 * j], uu.x);
                    fma2(a1, zp[2 * j + 1], uu.y);
                }
                float f0, f1, f2, f3;
                unpack2(a0, f0, f1);
                unpack2(a1, f2, f3);
                float val = xv[u] + (f0 + f1) + (f2 + f3) + bps[c];
                float r = rintf(val / so);
                r = fminf(fmaxf(r, -128.f), 127.f);
                ob[(size_t)c * NN] = r * so;
            }
        }
    }
}

// ---------------- launch ----------------------------------------------------------
extern "C" void kernel_launch(void* const* d_in, const int* in_sizes, int n_in,
                              void* d_out, int out_size) {
    const float* x     = (const float*)d_in[0];
    const float* wq    = (const float*)d_in[1];
    const float* bq    = (const float*)d_in[2];
    const float* wk    = (const float*)d_in[3];
    const float* bk    = (const float*)d_in[4];
    const float* wv    = (const float*)d_in[5];
    const float* bv    = (const float*)d_in[6];
    const float* wp    = (const float*)d_in[7];
    const float* bp    = (const float*)d_in[8];
    const float* s_in  = (const float*)d_in[9];
    const float* s_out = (const float*)d_in[10];
    float* out = (float*)d_out;

    const int smemB = (CC * 256 + CC * 96) * 4;
    cudaFuncSetAttribute(k_xq_qkv, cudaFuncAttributeMaxDynamicSharedMemorySize, smemB);
    cudaFuncSetAttribute(k_attn, cudaFuncAttributeMaxDynamicSharedMemorySize, ATTN_SMEM);

    k_xq_qkv<<<dim3(16, 8), 512, smemB>>>(x, wq, wk, wv, bq, bk, bv, s_in);
    k_attn<<<dim3(16, 8), 256, ATTN_SMEM>>>(wp, bp, s_in, s_out, out);
}

// round 15
// speedup vs baseline: 1.8836x; 1.1086x over previous
#include <cuda_runtime.h>
#include <cuda_fp16.h>
#include <math.h>
#include <stdint.h>

typedef unsigned long long ull;

// ---------------- f32x2 packed-math helpers ------------------------------------
__device__ __forceinline__ ull pack2(float lo, float hi) {
    ull r; asm("mov.b64 %0, {%1, %2};" : "=l"(r) : "f"(lo), "f"(hi)); return r;
}
__device__ __forceinline__ void unpack2(ull v, float& lo, float& hi) {
    asm("mov.b64 {%0, %1}, %2;" : "=f"(lo), "=f"(hi) : "l"(v));
}
__device__ __forceinline__ void fma2(ull& d, ull a, ull b) {
    asm("fma.rn.f32x2 %0, %1, %2, %0;" : "+l"(d) : "l"(a), "l"(b));
}

// ---------------- fp16 / mma helpers ---------------------------------------------
__device__ __forceinline__ uint32_t packh(float lo, float hi) {  // {lo->low16, hi->high16}
    uint32_t r; asm("cvt.rn.f16x2.f32 %0, %1, %2;" : "=r"(r) : "f"(hi), "f"(lo)); return r;
}
__device__ __forceinline__ float loH(uint32_t u) {
    float f; asm("{.reg .f16 l,h; mov.b32 {l,h}, %1; cvt.f32.f16 %0, l;}" : "=f"(f) : "r"(u));
    return f;
}
__device__ __forceinline__ float hiH(uint32_t u) {
    float f; asm("{.reg .f16 l,h; mov.b32 {l,h}, %1; cvt.f32.f16 %0, h;}" : "=f"(f) : "r"(u));
    return f;
}
__device__ __forceinline__ unsigned short f2h(float f) {
    unsigned short h; asm("cvt.rn.f16.f32 %0, %1;" : "=h"(h) : "f"(f)); return h;
}
__device__ __forceinline__ float h2f(unsigned short h) {
    float f; asm("cvt.f32.f16 %0, %1;" : "=f"(f) : "h"(h)); return f;
}
__device__ __forceinline__ float ex2f(float x) {
    float r; asm("ex2.approx.f32 %0, %1;" : "=f"(r) : "f"(x)); return r;
}

__device__ __forceinline__ uint32_t cvta_s(const void* p) {
    uint32_t a;
    asm("{ .reg .u64 t; cvta.to.shared.u64 t, %1; cvt.u32.u64 %0, t; }" : "=r"(a) : "l"(p));
    return a;
}
__device__ __forceinline__ void ldmx4(uint32_t* r, uint32_t a) {
    asm volatile("ldmatrix.sync.aligned.m8n8.x4.shared.b16 {%0,%1,%2,%3}, [%4];"
                 : "=r"(r[0]), "=r"(r[1]), "=r"(r[2]), "=r"(r[3]) : "r"(a));
}
__device__ __forceinline__ void mma16816(float* c, const uint32_t* a, uint32_t b0, uint32_t b1) {
    asm volatile(
        "mma.sync.aligned.m16n8k16.row.col.f32.f16.f16.f32 "
        "{%0,%1,%2,%3}, {%4,%5,%6,%7}, {%8,%9}, {%0,%1,%2,%3};"
        : "+f"(c[0]), "+f"(c[1]), "+f"(c[2]), "+f"(c[3])
        : "r"(a[0]), "r"(a[1]), "r"(a[2]), "r"(a[3]), "r"(b0), "r"(b1));
}
__device__ __forceinline__ void cpa16(uint32_t dst, const void* src) {
    asm volatile("cp.async.cg.shared.global [%0], [%1], 16;" :: "r"(dst), "l"(src) : "memory");
}
#define CP_COMMIT() asm volatile("cp.async.commit_group;" ::: "memory")
#define CP_WAIT0()  asm volatile("cp.async.wait_group 0;" ::: "memory")

// ---------------- problem constants -------------------------------------------
#define BB 8
#define CC 64
#define HC 32
#define NN 4096
#define LOG2E 1.4426950408889634f
#define PSHIFT 16.0f   // P' = 2^(S*log2e - 16); cancels exactly in O/l

// ---------------- device scratch -----------------------------------------------
__device__ __align__(16) unsigned short g_xq[BB * CC * NN];   // fp16 integer r (xq = r*si)
__device__ __align__(16) unsigned short g_qhi[BB * NN * HC];  // fp16(q*log2e) hi
__device__ __align__(16) unsigned short g_qlo[BB * NN * HC];  // fp16 residual
__device__ __align__(16) unsigned short g_khi[BB * NN * HC];  // fp16 K
__device__ __align__(16) unsigned short g_vthi[BB * HC * NN]; // fp16 V^T [b][d][n]

// ---------------- kernel B: tensor-core QKV (exact integer fp16 MMA) ------------
// grid (16, 8) = 128 blocks, 512 threads / 16 warps, 256 pixels/block.
// X (int r) and W (int w) are exact in fp16; f32-accum MMA sums are exact
// integers (< 2^24). One f32 scale+bias rounding in the epilogue.
#define XS_PITCH 144
#define WS_OFF   36864                 // Xs: 256 rows x 144B
#define QKV_SMEM (WS_OFF + 96 * 144)   // + Ws: 96 rows x 144B = 50688

__global__ void __launch_bounds__(512) k_xq_qkv(const float* __restrict__ x,
                                                const float* __restrict__ wq,
                                                const float* __restrict__ wk,
                                                const float* __restrict__ wv,
                                                const float* __restrict__ bq,
                                                const float* __restrict__ bk,
                                                const float* __restrict__ bv,
                                                const float* __restrict__ s_in_p) {
    extern __shared__ char smQ[];
    uint32_t sb = cvta_s(smQ);
    __shared__ float redw[48];
    const int t = threadIdx.x;
    const int w = t >> 5, lane = t & 31;
    const int b = blockIdx.y;
    const int n0 = blockIdx.x * 256;
    const float si = s_in_p[0];

    // ---- phase A: x fake-quant -> integer r as fp16 (smem A-operand + global) ----
    const float* xb = x + ((size_t)b * CC) * NN + n0;
    unsigned short* xqb = g_xq + ((size_t)b * CC) * NN + n0;
#pragma unroll 4
    for (int i = 0; i < 32; i++) {
        int idx = t + i * 512;
        int c = idx >> 8, p = idx & 255;
        float v = xb[c * NN + p];
        float r = rintf(v / si);
        r = fminf(fmaxf(r, -128.f), 127.f);
        unsigned short hr = f2h(r);            // exact (|r| <= 128)
        xqb[c * NN + p] = hr;
        *(unsigned short*)(smQ + p * XS_PITCH + c * 2) = hr;
    }

    // ---- weight max-abs (redundant per block; deterministic) ----
    float mx0 = 0.f, mx1 = 0.f, mx2 = 0.f;
    for (int i = t; i < CC * HC; i += 512) {
        mx0 = fmaxf(mx0, fabsf(wq[i]));
        mx1 = fmaxf(mx1, fabsf(wk[i]));
        mx2 = fmaxf(mx2, fabsf(wv[i]));
    }
#pragma unroll
    for (int s = 16; s; s >>= 1) {
        mx0 = fmaxf(mx0, __shfl_xor_sync(0xffffffffu, mx0, s));
        mx1 = fmaxf(mx1, __shfl_xor_sync(0xffffffffu, mx1, s));
        mx2 = fmaxf(mx2, __shfl_xor_sync(0xffffffffu, mx2, s));
    }
    if (lane == 0) { redw[w] = mx0; redw[16 + w] = mx1; redw[32 + w] = mx2; }
    __syncthreads();
    float s0 = 0.f, s1 = 0.f, s2 = 0.f;
#pragma unroll
    for (int i = 0; i < 16; i++) {
        s0 = fmaxf(s0, redw[i]);
        s1 = fmaxf(s1, redw[16 + i]);
        s2 = fmaxf(s2, redw[32 + i]);
    }
    s0 /= 127.f; s1 /= 127.f; s2 /= 127.f;

    // ---- Ws: integer weights as fp16, rows [0:32)=Q, [32:64)=K, [64:96)=V ----
    for (int i = t; i < CC * HC; i += 512) {
        int hc = i >> 6, c = i & 63;
        float q0 = fminf(fmaxf(rintf(wq[i] / s0), -127.f), 127.f);
        float q1 = fminf(fmaxf(rintf(wk[i] / s1), -127.f), 127.f);
        float q2 = fminf(fmaxf(rintf(wv[i] / s2), -127.f), 127.f);
        *(unsigned short*)(smQ + WS_OFF + hc * XS_PITCH + c * 2) = f2h(q0);
        *(unsigned short*)(smQ + WS_OFF + (32 + hc) * XS_PITCH + c * 2) = f2h(q1);
        *(unsigned short*)(smQ + WS_OFF + (64 + hc) * XS_PITCH + c * 2) = f2h(q2);
    }
    __syncthreads();

    // ---- GEMM: warp w -> px rows [16w, 16w+16), all 96 outputs ----
    uint32_t af[4][4];
    {
        uint32_t xa = sb + (uint32_t)((16 * w + (lane & 7) + ((lane >> 3) & 1) * 8) * XS_PITCH +
                                      ((lane >> 4) & 1) * 16);
#pragma unroll
        for (int kc = 0; kc < 4; kc++) ldmx4(af[kc], xa + kc * 32);
    }
    float acc[12][4];
#pragma unroll
    for (int nt = 0; nt < 12; nt++)
#pragma unroll
        for (int i = 0; i < 4; i++) acc[nt][i] = 0.f;

#pragma unroll
    for (int nt = 0; nt < 12; nt++) {
        uint32_t wa = sb + WS_OFF + (uint32_t)((8 * nt + (lane & 7)) * XS_PITCH + (lane >> 3) * 16);
        uint32_t bf[8];
        ldmx4(bf, wa);
        ldmx4(bf + 4, wa + 64);
        mma16816(acc[nt], af[0], bf[0], bf[1]);
        mma16816(acc[nt], af[1], bf[2], bf[3]);
        mma16816(acc[nt], af[2], bf[4], bf[5]);
        mma16816(acc[nt], af[3], bf[6], bf[7]);
    }

    // ---- epilogue: scale+bias, pack, store ----
    const float sqs = si * s0, sks = si * s1, svs = si * s2;
    const int row0 = 16 * w + (lane >> 2), row1 = row0 + 8;
    const int ch2 = 2 * (lane & 3);
    // Q (nt 0-3): (acc*sqs + bq) * LOG2E, fp16 hi + residual lo
#pragma unroll
    for (int nt = 0; nt < 4; nt++) {
        int ch = 8 * nt + ch2;
        float b0v = bq[ch], b1v = bq[ch + 1];
        float v00 = (acc[nt][0] * sqs + b0v) * LOG2E;
        float v01 = (acc[nt][1] * sqs + b1v) * LOG2E;
        float v10 = (acc[nt][2] * sqs + b0v) * LOG2E;
        float v11 = (acc[nt][3] * sqs + b1v) * LOG2E;
        uint32_t h0 = packh(v00, v01), h1 = packh(v10, v11);
        uint32_t l0 = packh(v00 - loH(h0), v01 - hiH(h0));
        uint32_t l1 = packh(v10 - loH(h1), v11 - hiH(h1));
        size_t o0 = ((size_t)b * NN + n0 + row0) * HC + ch;
        size_t o1 = ((size_t)b * NN + n0 + row1) * HC + ch;
        *(uint32_t*)(g_qhi + o0) = h0;
        *(uint32_t*)(g_qhi + o1) = h1;
        *(uint32_t*)(g_qlo + o0) = l0;
        *(uint32_t*)(g_qlo + o1) = l1;
    }
    // K (nt 4-7): single fp16
#pragma unroll
    for (int nt = 4; nt < 8; nt++) {
        int ch = 8 * (nt - 4) + ch2;
        float b0v = bk[ch], b1v = bk[ch + 1];
        uint32_t h0 = packh(acc[nt][0] * sks + b0v, acc[nt][1] * sks + b1v);
        uint32_t h1 = packh(acc[nt][2] * sks + b0v, acc[nt][3] * sks + b1v);
        *(uint32_t*)(g_khi + ((size_t)b * NN + n0 + row0) * HC + ch) = h0;
        *(uint32_t*)(g_khi + ((size_t)b * NN + n0 + row1) * HC + ch) = h1;
    }
    // V (nt 8-11): bounce through smem (reuses Xs region), then transposed store
    __syncthreads();   // everyone done reading Xs/Ws
    float* Vsm = (float*)smQ;   // [256 px][33] f32
#pragma unroll
    for (int nt = 8; nt < 12; nt++) {
        int d = 8 * (nt - 8) + ch2;
        float b0v = bv[d], b1v = bv[d + 1];
        Vsm[row0 * 33 + d] = acc[nt][0] * svs + b0v;
        Vsm[row0 * 33 + d + 1] = acc[nt][1] * svs + b1v;
        Vsm[row1 * 33 + d] = acc[nt][2] * svs + b0v;
        Vsm[row1 * 33 + d + 1] = acc[nt][3] * svs + b1v;
    }
    __syncthreads();
    {
        const int d = t >> 4, pxc = t & 15;    // 32 d x 16 px-chunks
        uint32_t u[8];
#pragma unroll
        for (int j = 0; j < 8; j++)
            u[j] = packh(Vsm[(pxc * 16 + 2 * j) * 33 + d],
                         Vsm[(pxc * 16 + 2 * j + 1) * 33 + d]);
        uint4* vo = (uint4*)(g_vthi + ((size_t)b * HC + d) * NN + n0 + pxc * 16);
        uint4 a; a.x = u[0]; a.y = u[1]; a.z = u[2]; a.w = u[3];
        uint4 c; c.x = u[4]; c.y = u[5]; c.z = u[6]; c.w = u[7];
        vo[0] = a;
        vo[1] = c;
    }
}

// ---------------- kernel C: HMMA flash attention + fused proj ---------------------
// grid (16, 8) = (q-tile 256, batch), 256 threads / 8 warps, 32 q-rows per warp.
// FP16 scheme: S = (Qhi+Qlo)*Kfp16 (2 MMA), O = Pfp16*Vfp16 (1 MMA)
// -> 192 MMA/SMSP/kt. P exponent-shifted by 2^-16 (cancels exactly in O/l).
#define SM_QHI 0            // 256 rows x 80B
#define SM_QLO 20480
#define SM_K   40960        // + buf*5120 : K 64x80
#define SM_V   51200        // + buf*4608 : V 32x144
#define SM_WP  60416        // wp quantized 64x32 f32
#define SM_BP  68608        // bp 64 f32
#define ATTN_SMEM 68864
// epilogue zs (256x34 f32 = 34816B) reuses the Q region

__global__ void __launch_bounds__(256, 1) k_attn(const float* __restrict__ wp,
                                                 const float* __restrict__ bp,
                                                 const float* __restrict__ s_in_p,
                                                 const float* __restrict__ s_out_p,
                                                 float* __restrict__ out) {
    extern __shared__ char sm[];
    __shared__ float redp[8];
    uint32_t sb = cvta_s(sm);
    const int t = threadIdx.x;
    const int w = t >> 5, lane = t & 31;
    const int b = blockIdx.y, qt = blockIdx.x;
    const int q0 = w * 32;

    const char* pkhi = (const char*)g_khi + (size_t)b * NN * 64;
    const char* pvhi = (const char*)g_vthi + (size_t)b * HC * (NN * 2);

    // staging: K 256 + V 256 = 512 cp.async of 16B; 256 threads x 2
    auto stageKV = [&](int kt) {
        uint32_t kb = sb + SM_K + (kt & 1) * 5120;
        uint32_t vb = sb + SM_V + (kt & 1) * 4608;
#pragma unroll
        for (int i = 0; i < 2; i++) {
            int idx = t + i * 256;
            if (idx < 256) {
                int row = idx >> 2, ch = idx & 3;
                cpa16(kb + row * 80 + ch * 16,
                      pkhi + (size_t)(kt * 64 + row) * 64 + ch * 16);
            } else {
                int rem = idx & 255;
                int d = rem >> 3, ch = rem & 7;
                cpa16(vb + d * 144 + ch * 16,
                      pvhi + (size_t)d * (NN * 2) + kt * 128 + ch * 16);
            }
        }
    };

    // ---- prologue: stage Q + KV(0); quantize wp while cp.async flies ----
    {
        const char* pqhi = (const char*)g_qhi + (size_t)b * NN * 64;
        const char* pqlo = (const char*)g_qlo + (size_t)b * NN * 64;
#pragma unroll
        for (int i = 0; i < 8; i++) {
            int idx = t + i * 256;
            int part = idx >> 10, rem = idx & 1023;
            int row = rem >> 2, ch = rem & 3;
            const char* src = (part ? pqlo : pqhi) + (size_t)(qt * 256 + row) * 64 + ch * 16;
            cpa16(sb + SM_QHI + part * 20480 + row * 80 + ch * 16, src);
        }
    }
    stageKV(0);
    CP_COMMIT();
    {
        float mxp = 0.f;
        for (int i = t; i < CC * HC; i += 256) mxp = fmaxf(mxp, fabsf(wp[i]));
#pragma unroll
        for (int s = 16; s; s >>= 1) mxp = fmaxf(mxp, __shfl_xor_sync(0xffffffffu, mxp, s));
        if (lane == 0) redp[w] = mxp;
        __syncthreads();
        float sp = fmaxf(fmaxf(fmaxf(redp[0], redp[1]), fmaxf(redp[2], redp[3])),
                         fmaxf(fmaxf(redp[4], redp[5]), fmaxf(redp[6], redp[7]))) / 127.f;
        float* wsp = (float*)(sm + SM_WP);
        for (int i = t; i < CC * HC; i += 256)
            wsp[i] = fminf(fmaxf(rintf(wp[i] / sp), -127.f), 127.f) * sp;
        if (t < CC) ((float*)(sm + SM_BP))[t] = bp[t];
    }
    CP_WAIT0();
    __syncthreads();

    // Q fragments (2 m-tiles x 2 k16 chunks, hi + lo) via ldmatrix.x4
    uint32_t qfh[2][2][4], qfl[2][2][4];
#pragma unroll
    for (int m = 0; m < 2; m++) {
        uint32_t qa = sb + SM_QHI +
            (uint32_t)((q0 + m * 16 + (lane & 7) + ((lane >> 3) & 1) * 8) * 80 +
                       ((lane >> 4) & 1) * 16);
        ldmx4(qfh[m][0], qa);
        ldmx4(qfh[m][1], qa + 32);
        ldmx4(qfl[m][0], qa + 20480);
        ldmx4(qfl[m][1], qa + 20480 + 32);
    }

    float O[2][4][4];
    float l_acc[2][2] = {{0.f, 0.f}, {0.f, 0.f}};
#pragma unroll
    for (int m = 0; m < 2; m++)
#pragma unroll
        for (int n = 0; n < 4; n++)
#pragma unroll
            for (int i = 0; i < 4; i++) O[m][n][i] = 0.f;

    // ---- main loop: 64 tiles of 64 keys ----
    for (int kt = 0; kt < 64; kt++) {
        uint32_t kb = sb + SM_K + (kt & 1) * 5120;
        uint32_t vb = sb + SM_V + (kt & 1) * 4608;
        if (kt < 63) { stageKV(kt + 1); CP_COMMIT(); }

        const uint32_t ka0 = kb + (uint32_t)((lane & 7) * 80 + (lane >> 3) * 16);

        // S = (Qhi + Qlo) * K, single-fp16 K, depth-1 K-fragment prefetch
        float S[2][8][4];
#pragma unroll
        for (int m = 0; m < 2; m++)
#pragma unroll
            for (int j = 0; j < 8; j++)
#pragma unroll
                for (int i = 0; i < 4; i++) S[m][j][i] = 0.f;

        uint32_t kf[2][4];
        ldmx4(kf[0], ka0);
#pragma unroll
        for (int j = 0; j < 8; j++) {
            const int cur = j & 1, nxt = cur ^ 1;
            if (j < 7) ldmx4(kf[nxt], ka0 + (uint32_t)((j + 1) * 8 * 80));
            // ks = 0 (dims 0-15)
            mma16816(S[0][j], qfh[0][0], kf[cur][0], kf[cur][1]);
            mma16816(S[0][j], qfl[0][0], kf[cur][0], kf[cur][1]);
            mma16816(S[1][j], qfh[1][0], kf[cur][0], kf[cur][1]);
            mma16816(S[1][j], qfl[1][0], kf[cur][0], kf[cur][1]);
            // ks = 1 (dims 16-31)
            mma16816(S[0][j], qfh[0][1], kf[cur][2], kf[cur][3]);
            mma16816(S[0][j], qfl[0][1], kf[cur][2], kf[cur][3]);
            mma16816(S[1][j], qfh[1][1], kf[cur][2], kf[cur][3]);
            mma16816(S[1][j], qfl[1][1], kf[cur][2], kf[cur][3]);
        }

        const uint32_t va0 = vb +
            (uint32_t)((((lane >> 4) & 1) * 8 + (lane & 7)) * 144 + ((lane >> 3) & 1) * 16);

        // PV in 16-key chunks: single-fp16 P (2^-16 shifted), V loads hoisted
#pragma unroll
        for (int kk = 0; kk < 4; kk++) {
            uint32_t vf[8];
            ldmx4(vf, va0 + kk * 32);                 // n 0-1
            ldmx4(vf + 4, va0 + kk * 32 + 16 * 144);  // n 2-3

            uint32_t phi[2][4];
#pragma unroll
            for (int m = 0; m < 2; m++) {
                const int j0 = 2 * kk, j1 = 2 * kk + 1;
                float e0 = ex2f(S[m][j0][0] - PSHIFT);
                float e1 = ex2f(S[m][j0][1] - PSHIFT);
                float e2 = ex2f(S[m][j0][2] - PSHIFT);
                float e3 = ex2f(S[m][j0][3] - PSHIFT);
                float e4 = ex2f(S[m][j1][0] - PSHIFT);
                float e5 = ex2f(S[m][j1][1] - PSHIFT);
                float e6 = ex2f(S[m][j1][2] - PSHIFT);
                float e7 = ex2f(S[m][j1][3] - PSHIFT);
                l_acc[m][0] += (e0 + e1) + (e4 + e5);
                l_acc[m][1] += (e2 + e3) + (e6 + e7);
                phi[m][0] = packh(e0, e1);
                phi[m][1] = packh(e2, e3);
                phi[m][2] = packh(e4, e5);
                phi[m][3] = packh(e6, e7);
            }
#pragma unroll
            for (int n = 0; n < 4; n++) {
                uint32_t b0 = vf[2 * n], b1 = vf[2 * n + 1];
                mma16816(O[0][n], phi[0], b0, b1);
                mma16816(O[1][n], phi[1], b0, b1);
            }
        }

        if (kt < 63) CP_WAIT0();
        __syncthreads();
    }

    // ---- epilogue 1: l-reduce, normalize (2^-16 shift cancels), fq z, stage ----
    const float si = s_in_p[0];
    const float so = s_out_p[0];
    float* zs = (float*)(sm + SM_QHI);
#pragma unroll
    for (int m = 0; m < 2; m++)
#pragma unroll
        for (int h = 0; h < 2; h++) {
            float lv = l_acc[m][h];
            lv += __shfl_xor_sync(0xffffffffu, lv, 1);
            lv += __shfl_xor_sync(0xffffffffu, lv, 2);
            float inv = 1.0f / lv;
            int row = q0 + m * 16 + (lane >> 2) + h * 8;
#pragma unroll
            for (int n = 0; n < 4; n++) {
                float z0 = O[m][n][h * 2 + 0] * inv;
                float z1 = O[m][n][h * 2 + 1] * inv;
                float r0 = fminf(fmaxf(rintf(z0 / si), -128.f), 127.f) * si;
                float r1 = fminf(fmaxf(rintf(z1 / si), -128.f), 127.f) * si;
                float2 u; u.x = r0; u.y = r1;
                *(float2*)(zs + row * 34 + n * 8 + (lane & 3) * 2) = u;
            }
        }
    __syncthreads();

    // ---- epilogue 2: output projection + residual + out fq (thread = pixel) ----
    {
        ull zp[16];
#pragma unroll
        for (int j = 0; j < 16; j++)
            zp[j] = pack2(zs[t * 34 + 2 * j], zs[t * 34 + 2 * j + 1]);
        const float* wsp = (const float*)(sm + SM_WP);
        const float* bps = (const float*)(sm + SM_BP);
        const unsigned short* xqb = g_xq + ((size_t)b * CC) * NN + qt * 256 + t;
        float* ob = out + ((size_t)b * CC) * NN + qt * 256 + t;
#pragma unroll
        for (int c0 = 0; c0 < CC; c0 += 16) {
            float xv[16];
#pragma unroll
            for (int u = 0; u < 16; u++) xv[u] = si * h2f(xqb[(size_t)(c0 + u) * NN]);
#pragma unroll
            for (int u = 0; u < 16; u++) {
                int c = c0 + u;
                ull a0 = 0ull, a1 = 0ull;
                const ulonglong2* wr = (const ulonglong2*)(wsp + c * HC);
#pragma unroll
                for (int j = 0; j < 8; j++) {
                    ulonglong2 uu = wr[j];
                    fma2(a0, zp[2 * j], uu.x);
                    fma2(a1, zp[2 * j + 1], uu.y);
                }
                float f0, f1, f2, f3;
                unpack2(a0, f0, f1);
                unpack2(a1, f2, f3);
                float val = xv[u] + (f0 + f1) + (f2 + f3) + bps[c];
                float r = rintf(val / so);
                r = fminf(fmaxf(r, -128.f), 127.f);
                ob[(size_t)c * NN] = r * so;
            }
        }
    }
}

// ---------------- launch ----------------------------------------------------------
extern "C" void kernel_launch(void* const* d_in, const int* in_sizes, int n_in,
                              void* d_out, int out_size) {
    const float* x     = (const float*)d_in[0];
    const float* wq    = (const float*)d_in[1];
    const float* bq    = (const float*)d_in[2];
    const float* wk    = (const float*)d_in[3];
    const float* bk    = (const float*)d_in[4];
    const float* wv    = (const float*)d_in[5];
    const float* bv    = (const float*)d_in[6];
    const float* wp    = (const float*)d_in[7];
    const float* bp    = (const float*)d_in[8];
    const float* s_in  = (const float*)d_in[9];
    const float* s_out = (const float*)d_in[10];
    float* out = (float*)d_out;

    cudaFuncSetAttribute(k_xq_qkv, cudaFuncAttributeMaxDynamicSharedMemorySize, QKV_SMEM);
    cudaFuncSetAttribute(k_attn, cudaFuncAttributeMaxDynamicSharedMemorySize, ATTN_SMEM);

    k_xq_qkv<<<dim3(16, 8), 512, QKV_SMEM>>>(x, wq, wk, wv, bq, bk, bv, s_in);
    k_attn<<<dim3(16, 8), 256, ATTN_SMEM>>>(wp, bp, s_in, s_out, out);
}

// round 16
// speedup vs baseline: 2.1206x; 1.1258x over previous
#include <cuda_runtime.h>
#include <cuda_fp16.h>
#include <math.h>
#include <stdint.h>

typedef unsigned long long ull;

// ---------------- f32x2 packed-math helpers ------------------------------------
__device__ __forceinline__ ull pack2(float lo, float hi) {
    ull r; asm("mov.b64 %0, {%1, %2};" : "=l"(r) : "f"(lo), "f"(hi)); return r;
}
__device__ __forceinline__ void unpack2(ull v, float& lo, float& hi) {
    asm("mov.b64 {%0, %1}, %2;" : "=f"(lo), "=f"(hi) : "l"(v));
}
__device__ __forceinline__ void fma2(ull& d, ull a, ull b) {
    asm("fma.rn.f32x2 %0, %1, %2, %0;" : "+l"(d) : "l"(a), "l"(b));
}

// ---------------- fp16 / mma helpers ---------------------------------------------
__device__ __forceinline__ uint32_t packh(float lo, float hi) {  // {lo->low16, hi->high16}
    uint32_t r; asm("cvt.rn.f16x2.f32 %0, %1, %2;" : "=r"(r) : "f"(hi), "f"(lo)); return r;
}
__device__ __forceinline__ unsigned short f2h(float f) {
    unsigned short h; asm("cvt.rn.f16.f32 %0, %1;" : "=h"(h) : "f"(f)); return h;
}
__device__ __forceinline__ float h2f(unsigned short h) {
    float f; asm("cvt.f32.f16 %0, %1;" : "=f"(f) : "h"(h)); return f;
}
__device__ __forceinline__ float ex2f(float x) {
    float r; asm("ex2.approx.f32 %0, %1;" : "=f"(r) : "f"(x)); return r;
}

__device__ __forceinline__ uint32_t cvta_s(const void* p) {
    uint32_t a;
    asm("{ .reg .u64 t; cvta.to.shared.u64 t, %1; cvt.u32.u64 %0, t; }" : "=r"(a) : "l"(p));
    return a;
}
__device__ __forceinline__ void ldmx4(uint32_t* r, uint32_t a) {
    asm volatile("ldmatrix.sync.aligned.m8n8.x4.shared.b16 {%0,%1,%2,%3}, [%4];"
                 : "=r"(r[0]), "=r"(r[1]), "=r"(r[2]), "=r"(r[3]) : "r"(a));
}
__device__ __forceinline__ void mma16816(float* c, const uint32_t* a, uint32_t b0, uint32_t b1) {
    asm volatile(
        "mma.sync.aligned.m16n8k16.row.col.f32.f16.f16.f32 "
        "{%0,%1,%2,%3}, {%4,%5,%6,%7}, {%8,%9}, {%0,%1,%2,%3};"
        : "+f"(c[0]), "+f"(c[1]), "+f"(c[2]), "+f"(c[3])
        : "r"(a[0]), "r"(a[1]), "r"(a[2]), "r"(a[3]), "r"(b0), "r"(b1));
}
__device__ __forceinline__ void cpa16(uint32_t dst, const void* src) {
    asm volatile("cp.async.cg.shared.global [%0], [%1], 16;" :: "r"(dst), "l"(src) : "memory");
}
#define CP_COMMIT() asm volatile("cp.async.commit_group;" ::: "memory")
#define CP_WAIT0()  asm volatile("cp.async.wait_group 0;" ::: "memory")

// ---------------- problem constants -------------------------------------------
#define BB 8
#define CC 64
#define HC 32
#define NN 4096
#define LOG2E 1.4426950408889634f
#define PSHIFT 16.0f   // P' = 2^(S*log2e - 16); cancels exactly in O/l

// ---------------- device scratch -----------------------------------------------
__device__ __align__(16) unsigned short g_xq[BB * CC * NN];   // fp16 integer r (xq = r*si)
__device__ __align__(16) unsigned short g_qhi[BB * NN * HC];  // fp16(q*log2e)
__device__ __align__(16) unsigned short g_khi[BB * NN * HC];  // fp16 K
__device__ __align__(16) unsigned short g_vthi[BB * HC * NN]; // fp16 V^T [b][d][n]

// ---------------- kernel B: tensor-core QKV (exact integer fp16 MMA) ------------
// grid (16, 8) = 128 blocks, 512 threads / 16 warps, 256 pixels/block.
#define XS_PITCH 144
#define WS_OFF   36864                 // Xs: 256 rows x 144B
#define QKV_SMEM (WS_OFF + 96 * 144)   // + Ws: 96 rows x 144B = 50688

__global__ void __launch_bounds__(512) k_xq_qkv(const float* __restrict__ x,
                                                const float* __restrict__ wq,
                                                const float* __restrict__ wk,
                                                const float* __restrict__ wv,
                                                const float* __restrict__ bq,
                                                const float* __restrict__ bk,
                                                const float* __restrict__ bv,
                                                const float* __restrict__ s_in_p) {
    extern __shared__ char smQ[];
    uint32_t sb = cvta_s(smQ);
    __shared__ float redw[48];
    const int t = threadIdx.x;
    const int w = t >> 5, lane = t & 31;
    const int b = blockIdx.y;
    const int n0 = blockIdx.x * 256;
    const float si = s_in_p[0];

    // ---- phase A: x fake-quant -> integer r as fp16 (smem A-operand + global) ----
    const float* xb = x + ((size_t)b * CC) * NN + n0;
    unsigned short* xqb = g_xq + ((size_t)b * CC) * NN + n0;
#pragma unroll 4
    for (int i = 0; i < 32; i++) {
        int idx = t + i * 512;
        int c = idx >> 8, p = idx & 255;
        float v = xb[c * NN + p];
        float r = rintf(v / si);
        r = fminf(fmaxf(r, -128.f), 127.f);
        unsigned short hr = f2h(r);            // exact (|r| <= 128)
        xqb[c * NN + p] = hr;
        *(unsigned short*)(smQ + p * XS_PITCH + c * 2) = hr;
    }

    // ---- weight max-abs (redundant per block; deterministic) ----
    float mx0 = 0.f, mx1 = 0.f, mx2 = 0.f;
    for (int i = t; i < CC * HC; i += 512) {
        mx0 = fmaxf(mx0, fabsf(wq[i]));
        mx1 = fmaxf(mx1, fabsf(wk[i]));
        mx2 = fmaxf(mx2, fabsf(wv[i]));
    }
#pragma unroll
    for (int s = 16; s; s >>= 1) {
        mx0 = fmaxf(mx0, __shfl_xor_sync(0xffffffffu, mx0, s));
        mx1 = fmaxf(mx1, __shfl_xor_sync(0xffffffffu, mx1, s));
        mx2 = fmaxf(mx2, __shfl_xor_sync(0xffffffffu, mx2, s));
    }
    if (lane == 0) { redw[w] = mx0; redw[16 + w] = mx1; redw[32 + w] = mx2; }
    __syncthreads();
    float s0 = 0.f, s1 = 0.f, s2 = 0.f;
#pragma unroll
    for (int i = 0; i < 16; i++) {
        s0 = fmaxf(s0, redw[i]);
        s1 = fmaxf(s1, redw[16 + i]);
        s2 = fmaxf(s2, redw[32 + i]);
    }
    s0 /= 127.f; s1 /= 127.f; s2 /= 127.f;

    // ---- Ws: integer weights as fp16, rows [0:32)=Q, [32:64)=K, [64:96)=V ----
    for (int i = t; i < CC * HC; i += 512) {
        int hc = i >> 6, c = i & 63;
        float q0 = fminf(fmaxf(rintf(wq[i] / s0), -127.f), 127.f);
        float q1 = fminf(fmaxf(rintf(wk[i] / s1), -127.f), 127.f);
        float q2 = fminf(fmaxf(rintf(wv[i] / s2), -127.f), 127.f);
        *(unsigned short*)(smQ + WS_OFF + hc * XS_PITCH + c * 2) = f2h(q0);
        *(unsigned short*)(smQ + WS_OFF + (32 + hc) * XS_PITCH + c * 2) = f2h(q1);
        *(unsigned short*)(smQ + WS_OFF + (64 + hc) * XS_PITCH + c * 2) = f2h(q2);
    }
    __syncthreads();

    // ---- GEMM: warp w -> px rows [16w, 16w+16), all 96 outputs ----
    uint32_t af[4][4];
    {
        uint32_t xa = sb + (uint32_t)((16 * w + (lane & 7) + ((lane >> 3) & 1) * 8) * XS_PITCH +
                                      ((lane >> 4) & 1) * 16);
#pragma unroll
        for (int kc = 0; kc < 4; kc++) ldmx4(af[kc], xa + kc * 32);
    }
    float acc[12][4];
#pragma unroll
    for (int nt = 0; nt < 12; nt++)
#pragma unroll
        for (int i = 0; i < 4; i++) acc[nt][i] = 0.f;

#pragma unroll
    for (int nt = 0; nt < 12; nt++) {
        uint32_t wa = sb + WS_OFF + (uint32_t)((8 * nt + (lane & 7)) * XS_PITCH + (lane >> 3) * 16);
        uint32_t bf[8];
        ldmx4(bf, wa);
        ldmx4(bf + 4, wa + 64);
        mma16816(acc[nt], af[0], bf[0], bf[1]);
        mma16816(acc[nt], af[1], bf[2], bf[3]);
        mma16816(acc[nt], af[2], bf[4], bf[5]);
        mma16816(acc[nt], af[3], bf[6], bf[7]);
    }

    // ---- epilogue: scale+bias, pack, store ----
    const float sqs = si * s0, sks = si * s1, svs = si * s2;
    const int row0 = 16 * w + (lane >> 2), row1 = row0 + 8;
    const int ch2 = 2 * (lane & 3);
    // Q (nt 0-3): (acc*sqs + bq) * LOG2E, single fp16
#pragma unroll
    for (int nt = 0; nt < 4; nt++) {
        int ch = 8 * nt + ch2;
        float b0v = bq[ch], b1v = bq[ch + 1];
        uint32_t h0 = packh((acc[nt][0] * sqs + b0v) * LOG2E,
                            (acc[nt][1] * sqs + b1v) * LOG2E);
        uint32_t h1 = packh((acc[nt][2] * sqs + b0v) * LOG2E,
                            (acc[nt][3] * sqs + b1v) * LOG2E);
        *(uint32_t*)(g_qhi + ((size_t)b * NN + n0 + row0) * HC + ch) = h0;
        *(uint32_t*)(g_qhi + ((size_t)b * NN + n0 + row1) * HC + ch) = h1;
    }
    // K (nt 4-7): single fp16
#pragma unroll
    for (int nt = 4; nt < 8; nt++) {
        int ch = 8 * (nt - 4) + ch2;
        float b0v = bk[ch], b1v = bk[ch + 1];
        uint32_t h0 = packh(acc[nt][0] * sks + b0v, acc[nt][1] * sks + b1v);
        uint32_t h1 = packh(acc[nt][2] * sks + b0v, acc[nt][3] * sks + b1v);
        *(uint32_t*)(g_khi + ((size_t)b * NN + n0 + row0) * HC + ch) = h0;
        *(uint32_t*)(g_khi + ((size_t)b * NN + n0 + row1) * HC + ch) = h1;
    }
    // V (nt 8-11): bounce through smem (reuses Xs region), then transposed store
    __syncthreads();   // everyone done reading Xs/Ws
    float* Vsm = (float*)smQ;   // [256 px][33] f32
#pragma unroll
    for (int nt = 8; nt < 12; nt++) {
        int d = 8 * (nt - 8) + ch2;
        float b0v = bv[d], b1v = bv[d + 1];
        Vsm[row0 * 33 + d] = acc[nt][0] * svs + b0v;
        Vsm[row0 * 33 + d + 1] = acc[nt][1] * svs + b1v;
        Vsm[row1 * 33 + d] = acc[nt][2] * svs + b0v;
        Vsm[row1 * 33 + d + 1] = acc[nt][3] * svs + b1v;
    }
    __syncthreads();
    {
        const int d = t >> 4, pxc = t & 15;    // 32 d x 16 px-chunks
        uint32_t u[8];
#pragma unroll
        for (int j = 0; j < 8; j++)
            u[j] = packh(Vsm[(pxc * 16 + 2 * j) * 33 + d],
                         Vsm[(pxc * 16 + 2 * j + 1) * 33 + d]);
        uint4* vo = (uint4*)(g_vthi + ((size_t)b * HC + d) * NN + n0 + pxc * 16);
        uint4 a; a.x = u[0]; a.y = u[1]; a.z = u[2]; a.w = u[3];
        uint4 c; c.x = u[4]; c.y = u[5]; c.z = u[6]; c.w = u[7];
        vo[0] = a;
        vo[1] = c;
    }
}

// ---------------- kernel C: HMMA flash attention + fused proj ---------------------
// grid (16, 8) = (q-tile 256, batch), 256 threads / 8 warps, 32 q-rows per warp.
// All-single-fp16 scheme: S = Q*K (1 MMA), O = P*V (1 MMA) -> 128 MMA/SMSP/kt.
// P exponent-shifted by 2^-16 (cancels exactly in O/l).
#define SM_QHI 0            // 256 rows x 80B = 20480
#define SM_K   20480        // + buf*5120 : K 64x80
#define SM_V   30720        // + buf*4608 : V 32x144
#define SM_WP  39936        // wp quantized 64x32 f32
#define SM_BP  48128        // bp 64 f32
#define ATTN_SMEM 48384
// epilogue zs (256x34 f32 = 34816B) reuses smem from offset 0 (Q/K/V regions)

__global__ void __launch_bounds__(256, 1) k_attn(const float* __restrict__ wp,
                                                 const float* __restrict__ bp,
                                                 const float* __restrict__ s_in_p,
                                                 const float* __restrict__ s_out_p,
                                                 float* __restrict__ out) {
    extern __shared__ char sm[];
    __shared__ float redp[8];
    uint32_t sb = cvta_s(sm);
    const int t = threadIdx.x;
    const int w = t >> 5, lane = t & 31;
    const int b = blockIdx.y, qt = blockIdx.x;
    const int q0 = w * 32;

    const char* pkhi = (const char*)g_khi + (size_t)b * NN * 64;
    const char* pvhi = (const char*)g_vthi + (size_t)b * HC * (NN * 2);

    // staging: K 256 + V 256 = 512 cp.async of 16B; 256 threads x 2
    auto stageKV = [&](int kt) {
        uint32_t kb = sb + SM_K + (kt & 1) * 5120;
        uint32_t vb = sb + SM_V + (kt & 1) * 4608;
#pragma unroll
        for (int i = 0; i < 2; i++) {
            int idx = t + i * 256;
            if (idx < 256) {
                int row = idx >> 2, ch = idx & 3;
                cpa16(kb + row * 80 + ch * 16,
                      pkhi + (size_t)(kt * 64 + row) * 64 + ch * 16);
            } else {
                int rem = idx & 255;
                int d = rem >> 3, ch = rem & 7;
                cpa16(vb + d * 144 + ch * 16,
                      pvhi + (size_t)d * (NN * 2) + kt * 128 + ch * 16);
            }
        }
    };

    // ---- prologue: stage Q + KV(0); quantize wp while cp.async flies ----
    {
        const char* pqhi = (const char*)g_qhi + (size_t)b * NN * 64;
#pragma unroll
        for (int i = 0; i < 4; i++) {
            int idx = t + i * 256;
            int row = idx >> 2, ch = idx & 3;
            cpa16(sb + SM_QHI + row * 80 + ch * 16,
                  pqhi + (size_t)(qt * 256 + row) * 64 + ch * 16);
        }
    }
    stageKV(0);
    CP_COMMIT();
    {
        float mxp = 0.f;
        for (int i = t; i < CC * HC; i += 256) mxp = fmaxf(mxp, fabsf(wp[i]));
#pragma unroll
        for (int s = 16; s; s >>= 1) mxp = fmaxf(mxp, __shfl_xor_sync(0xffffffffu, mxp, s));
        if (lane == 0) redp[w] = mxp;
        __syncthreads();
        float sp = fmaxf(fmaxf(fmaxf(redp[0], redp[1]), fmaxf(redp[2], redp[3])),
                         fmaxf(fmaxf(redp[4], redp[5]), fmaxf(redp[6], redp[7]))) / 127.f;
        float* wsp = (float*)(sm + SM_WP);
        for (int i = t; i < CC * HC; i += 256)
            wsp[i] = fminf(fmaxf(rintf(wp[i] / sp), -127.f), 127.f) * sp;
        if (t < CC) ((float*)(sm + SM_BP))[t] = bp[t];
    }
    CP_WAIT0();
    __syncthreads();

    // Q fragments (2 m-tiles x 2 k16 chunks, single fp16) via ldmatrix.x4
    uint32_t qfh[2][2][4];
#pragma unroll
    for (int m = 0; m < 2; m++) {
        uint32_t qa = sb + SM_QHI +
            (uint32_t)((q0 + m * 16 + (lane & 7) + ((lane >> 3) & 1) * 8) * 80 +
                       ((lane >> 4) & 1) * 16);
        ldmx4(qfh[m][0], qa);
        ldmx4(qfh[m][1], qa + 32);
    }

    float O[2][4][4];
    float l_acc[2][2] = {{0.f, 0.f}, {0.f, 0.f}};
#pragma unroll
    for (int m = 0; m < 2; m++)
#pragma unroll
        for (int n = 0; n < 4; n++)
#pragma unroll
            for (int i = 0; i < 4; i++) O[m][n][i] = 0.f;

    // ---- main loop: 64 tiles of 64 keys ----
    for (int kt = 0; kt < 64; kt++) {
        uint32_t kb = sb + SM_K + (kt & 1) * 5120;
        uint32_t vb = sb + SM_V + (kt & 1) * 4608;
        if (kt < 63) { stageKV(kt + 1); CP_COMMIT(); }

        const uint32_t ka0 = kb + (uint32_t)((lane & 7) * 80 + (lane >> 3) * 16);

        // S = Q * K, single fp16 both sides, depth-1 K-fragment prefetch
        float S[2][8][4];
#pragma unroll
        for (int m = 0; m < 2; m++)
#pragma unroll
            for (int j = 0; j < 8; j++)
#pragma unroll
                for (int i = 0; i < 4; i++) S[m][j][i] = 0.f;

        uint32_t kf[2][4];
        ldmx4(kf[0], ka0);
#pragma unroll
        for (int j = 0; j < 8; j++) {
            const int cur = j & 1, nxt = cur ^ 1;
            if (j < 7) ldmx4(kf[nxt], ka0 + (uint32_t)((j + 1) * 8 * 80));
            mma16816(S[0][j], qfh[0][0], kf[cur][0], kf[cur][1]);
            mma16816(S[1][j], qfh[1][0], kf[cur][0], kf[cur][1]);
            mma16816(S[0][j], qfh[0][1], kf[cur][2], kf[cur][3]);
            mma16816(S[1][j], qfh[1][1], kf[cur][2], kf[cur][3]);
        }

        const uint32_t va0 = vb +
            (uint32_t)((((lane >> 4) & 1) * 8 + (lane & 7)) * 144 + ((lane >> 3) & 1) * 16);

        // PV in 16-key chunks: single-fp16 P (2^-16 shifted), V loads hoisted
#pragma unroll
        for (int kk = 0; kk < 4; kk++) {
            uint32_t vf[8];
            ldmx4(vf, va0 + kk * 32);                 // n 0-1
            ldmx4(vf + 4, va0 + kk * 32 + 16 * 144);  // n 2-3

            uint32_t phi[2][4];
#pragma unroll
            for (int m = 0; m < 2; m++) {
                const int j0 = 2 * kk, j1 = 2 * kk + 1;
                float e0 = ex2f(S[m][j0][0] - PSHIFT);
                float e1 = ex2f(S[m][j0][1] - PSHIFT);
                float e2 = ex2f(S[m][j0][2] - PSHIFT);
                float e3 = ex2f(S[m][j0][3] - PSHIFT);
                float e4 = ex2f(S[m][j1][0] - PSHIFT);
                float e5 = ex2f(S[m][j1][1] - PSHIFT);
                float e6 = ex2f(S[m][j1][2] - PSHIFT);
                float e7 = ex2f(S[m][j1][3] - PSHIFT);
                l_acc[m][0] += (e0 + e1) + (e4 + e5);
                l_acc[m][1] += (e2 + e3) + (e6 + e7);
                phi[m][0] = packh(e0, e1);
                phi[m][1] = packh(e2, e3);
                phi[m][2] = packh(e4, e5);
                phi[m][3] = packh(e6, e7);
            }
#pragma unroll
            for (int n = 0; n < 4; n++) {
                uint32_t b0 = vf[2 * n], b1 = vf[2 * n + 1];
                mma16816(O[0][n], phi[0], b0, b1);
                mma16816(O[1][n], phi[1], b0, b1);
            }
        }

        if (kt < 63) CP_WAIT0();
        __syncthreads();
    }

    // ---- epilogue 1: l-reduce, normalize (2^-16 shift cancels), fq z, stage ----
    const float si = s_in_p[0];
    const float so = s_out_p[0];
    float* zs = (float*)(sm + SM_QHI);
#pragma unroll
    for (int m = 0; m < 2; m++)
#pragma unroll
        for (int h = 0; h < 2; h++) {
            float lv = l_acc[m][h];
            lv += __shfl_xor_sync(0xffffffffu, lv, 1);
            lv += __shfl_xor_sync(0xffffffffu, lv, 2);
            float inv = 1.0f / lv;
            int row = q0 + m * 16 + (lane >> 2) + h * 8;
#pragma unroll
            for (int n = 0; n < 4; n++) {
                float z0 = O[m][n][h * 2 + 0] * inv;
                float z1 = O[m][n][h * 2 + 1] * inv;
                float r0 = fminf(fmaxf(rintf(z0 / si), -128.f), 127.f) * si;
                float r1 = fminf(fmaxf(rintf(z1 / si), -128.f), 127.f) * si;
                float2 u; u.x = r0; u.y = r1;
                *(float2*)(zs + row * 34 + n * 8 + (lane & 3) * 2) = u;
            }
        }
    __syncthreads();

    // ---- epilogue 2: output projection + residual + out fq (thread = pixel) ----
    {
        ull zp[16];
#pragma unroll
        for (int j = 0; j < 16; j++)
            zp[j] = pack2(zs[t * 34 + 2 * j], zs[t * 34 + 2 * j + 1]);
        const float* wsp = (const float*)(sm + SM_WP);
        const float* bps = (const float*)(sm + SM_BP);
        const unsigned short* xqb = g_xq + ((size_t)b * CC) * NN + qt * 256 + t;
        float* ob = out + ((size_t)b * CC) * NN + qt * 256 + t;
#pragma unroll
        for (int c0 = 0; c0 < CC; c0 += 16) {
            float xv[16];
#pragma unroll
            for (int u = 0; u < 16; u++) xv[u] = si * h2f(xqb[(size_t)(c0 + u) * NN]);
#pragma unroll
            for (int u = 0; u < 16; u++) {
                int c = c0 + u;
                ull a0 = 0ull, a1 = 0ull;
                const ulonglong2* wr = (const ulonglong2*)(wsp + c * HC);
#pragma unroll
                for (int j = 0; j < 8; j++) {
                    ulonglong2 uu = wr[j];
                    fma2(a0, zp[2 * j], uu.x);
                    fma2(a1, zp[2 * j + 1], uu.y);
                }
                float f0, f1, f2, f3;
                unpack2(a0, f0, f1);
                unpack2(a1, f2, f3);
                float val = xv[u] + (f0 + f1) + (f2 + f3) + bps[c];
                float r = rintf(val / so);
                r = fminf(fmaxf(r, -128.f), 127.f);
                ob[(size_t)c * NN] = r * so;
            }
        }
    }
}

// ---------------- launch ----------------------------------------------------------
extern "C" void kernel_launch(void* const* d_in, const int* in_sizes, int n_in,
                              void* d_out, int out_size) {
    const float* x     = (const float*)d_in[0];
    const float* wq    = (const float*)d_in[1];
    const float* bq    = (const float*)d_in[2];
    const float* wk    = (const float*)d_in[3];
    const float* bk    = (const float*)d_in[4];
    const float* wv    = (const float*)d_in[5];
    const float* bv    = (const float*)d_in[6];
    const float* wp    = (const float*)d_in[7];
    const float* bp    = (const float*)d_in[8];
    const float* s_in  = (const float*)d_in[9];
    const float* s_out = (const float*)d_in[10];
    float* out = (float*)d_out;

    cudaFuncSetAttribute(k_xq_qkv, cudaFuncAttributeMaxDynamicSharedMemorySize, QKV_SMEM);
    cudaFuncSetAttribute(k_attn, cudaFuncAttributeMaxDynamicSharedMemorySize, ATTN_SMEM);

    k_xq_qkv<<<dim3(16, 8), 512, QKV_SMEM>>>(x, wq, wk, wv, bq, bk, bv, s_in);
    k_attn<<<dim3(16, 8), 256, ATTN_SMEM>>>(wp, bp, s_in, s_out, out);
}